// round 1
// baseline (speedup 1.0000x reference)
#include <cuda_runtime.h>

#define BB  2
#define CC  256
#define NN  2304
#define HH  8
#define DHH 64
#define OO  512
#define NK  2305
#define NKP 2368   // 1 null + 2304 + 63 pad = 74 * 32

// ---- scratch (device globals; no allocation allowed) ----
__device__ float g_norm[BB*CC*NN];        // normalized fmap, (b,c,n)
__device__ float g_scale[BB*NN];          // per-pixel rms scale
__device__ float g_k[BB*HH*DHH*NKP];      // keys (b,h,d,j): j=0 null, 1..2304 = proj, pad 0
__device__ float g_v[BB*HH*DHH*NKP];
__device__ float g_k2[BB*HH*NKP];         // |k_j|^2 (1e9 on pad)
__device__ float g_att[BB*OO*NN];         // attention output (b, h*64+d, i)

// ===================== RMSNorm =====================
__global__ __launch_bounds__(256) void rms_sumsq_kernel(const float* __restrict__ fmap) {
    __shared__ float part[8][32];
    int b  = blockIdx.x / 72;
    int p0 = (blockIdx.x % 72) * 32;
    int w = threadIdx.x >> 5, l = threadIdx.x & 31;
    int p = p0 + l;
    float s = 0.f;
    #pragma unroll
    for (int c = w; c < CC; c += 8) {
        float v = fmap[(b*CC + c)*NN + p];
        s += v*v;
    }
    part[w][l] = s;
    __syncthreads();
    if (w == 0) {
        float t = 0.f;
        #pragma unroll
        for (int i = 0; i < 8; i++) t += part[i][l];
        // sqrt(256) = 16 folded in
        g_scale[b*NN + p] = 16.0f / fmaxf(sqrtf(t), 1e-12f);
    }
}

__global__ __launch_bounds__(256) void rms_norm_kernel(const float* __restrict__ fmap,
                                                       const float* __restrict__ gamma) {
    int idx = blockIdx.x*256 + threadIdx.x;
    int p = idx % NN;
    int c = (idx / NN) % CC;
    int b = idx / (CC*NN);
    g_norm[idx] = fmap[idx] * g_scale[b*NN + p] * gamma[c];
}

// ===================== QK / V projection GEMM =====================
// C = W(512x256) @ norm(256x2304), written to g_k / g_v at j = i+1 (row stride NKP)
__global__ __launch_bounds__(256) void proj_gemm_kernel(const float* __restrict__ wqk,
                                                        const float* __restrict__ wv) {
    int z = blockIdx.z;
    int b = z >> 1;
    const float* W = (z & 1) ? wv : wqk;
    float* dst = ((z & 1) ? g_v : g_k) + (size_t)b*HH*DHH*NKP;
    int o0 = blockIdx.y * 64;
    int n0 = blockIdx.x * 64;
    __shared__ float As[16][64];   // [k][o]
    __shared__ float Bs[16][64];   // [k][n]
    int tid = threadIdx.x;
    int tx = tid & 15, ty = tid >> 4;
    float acc[4][4] = {};
    for (int kt = 0; kt < CC; kt += 16) {
        #pragma unroll
        for (int e = tid; e < 1024; e += 256) {
            int r = e >> 4, c = e & 15;
            As[c][r] = W[(o0 + r)*CC + kt + c];
        }
        #pragma unroll
        for (int e = tid; e < 1024; e += 256) {
            int c = e >> 6, j = e & 63;
            Bs[c][j] = g_norm[(size_t)(b*CC + kt + c)*NN + n0 + j];
        }
        __syncthreads();
        #pragma unroll
        for (int kk = 0; kk < 16; kk++) {
            float4 av = *(const float4*)&As[kk][ty*4];
            float4 bv = *(const float4*)&Bs[kk][tx*4];
            float a_[4] = {av.x, av.y, av.z, av.w};
            float b_[4] = {bv.x, bv.y, bv.z, bv.w};
            #pragma unroll
            for (int a = 0; a < 4; a++)
                #pragma unroll
                for (int e = 0; e < 4; e++)
                    acc[a][e] += a_[a]*b_[e];
        }
        __syncthreads();
    }
    #pragma unroll
    for (int a = 0; a < 4; a++)
        #pragma unroll
        for (int e = 0; e < 4; e++)
            dst[(size_t)(o0 + ty*4 + a)*NKP + n0 + tx*4 + e + 1] = acc[a][e];
}

// ===================== null token + pad fill =====================
__global__ void fill_null_kernel(const float* __restrict__ null_kv) {
    int tid = blockIdx.x*256 + threadIdx.x;
    if (tid >= BB*HH*DHH) return;
    int d  = tid & 63;
    int bh = tid >> 6;
    int h  = bh & 7;
    size_t row = (size_t)(bh*DHH + d) * NKP;
    g_k[row] = null_kv[h*DHH + d];
    g_v[row] = null_kv[HH*DHH + h*DHH + d];
    for (int j = NK; j < NKP; j++) { g_k[row + j] = 0.f; g_v[row + j] = 0.f; }
}

// ===================== k2 =====================
__global__ __launch_bounds__(256) void k2_kernel() {
    int tid = blockIdx.x*256 + threadIdx.x;   // BB*HH*NKP = 37888
    int j  = tid % NKP;
    int bh = tid / NKP;
    if (j >= NK) { g_k2[tid] = 1e9f; return; }
    const float* base = g_k + (size_t)bh*DHH*NKP + j;
    float s = 0.f;
    #pragma unroll
    for (int d = 0; d < DHH; d++) { float v = base[(size_t)d*NKP]; s += v*v; }
    g_k2[tid] = s;
}

// ===================== attention =====================
__global__ __launch_bounds__(256) void attn_kernel() {
    int bh  = blockIdx.y;          // 16 = b*8+h
    int i0g = blockIdx.x * 64;     // 36 query tiles
    int tid = threadIdx.x;
    int tx = tid & 15, ty = tid >> 4;
    __shared__ float Qs[64*64];    // [d][i]
    __shared__ float Ks[64*32];    // [d][j]
    __shared__ float Vs[64*32];    // [d][j]
    __shared__ float Ps[64*33];    // [i][j] (+pad)
    __shared__ float q2s[64];
    __shared__ float rden[64];

    const float* kbase  = g_k  + (size_t)bh*DHH*NKP;
    const float* vbase  = g_v  + (size_t)bh*DHH*NKP;
    const float* k2base = g_k2 + (size_t)bh*NKP;

    for (int e = tid; e < 4096; e += 256) {
        int d = e >> 6, i = e & 63;
        Qs[e] = kbase[(size_t)d*NKP + i0g + i + 1];   // q_i = k_{i+1}
    }
    if (tid < 64) q2s[tid] = k2base[i0g + tid + 1];

    float oacc[4][4] = {};
    float den[4] = {};
    int ib = tx*4;     // query sub-tile
    int jb = ty*2;     // key sub-tile (stage 1)
    int d0 = ty*4;     // dim sub-tile (stage 2)
    __syncthreads();

    for (int kb = 0; kb < NKP/32; kb++) {
        int j0 = kb*32;
        #pragma unroll
        for (int e = tid; e < 2048; e += 256) {
            int d = e >> 5, j = e & 31;
            Ks[e] = kbase[(size_t)d*NKP + j0 + j];
            Vs[e] = vbase[(size_t)d*NKP + j0 + j];
        }
        __syncthreads();

        // stage 1: cross[i][j] = sum_d Q[d][i] K[d][j]
        float acc[4][2] = {};
        #pragma unroll 8
        for (int d = 0; d < 64; d++) {
            float4 q = *(const float4*)&Qs[d*64 + ib];
            float2 k = *(const float2*)&Ks[d*32 + jb];
            acc[0][0] += q.x*k.x; acc[0][1] += q.x*k.y;
            acc[1][0] += q.y*k.x; acc[1][1] += q.y*k.y;
            acc[2][0] += q.z*k.x; acc[2][1] += q.z*k.y;
            acc[3][0] += q.w*k.x; acc[3][1] += q.w*k.y;
        }
        float k2v0 = k2base[j0 + jb];
        float k2v1 = k2base[j0 + jb + 1];
        #pragma unroll
        for (int a = 0; a < 4; a++) {
            int ig = i0g + ib + a;
            float q2 = q2s[ib + a];
            #pragma unroll
            for (int jj = 0; jj < 2; jj++) {
                int jg = j0 + jb + jj;
                float k2v = jj ? k2v1 : k2v0;
                float d2 = fmaxf(q2 + k2v - 2.0f*acc[a][jj], 0.0f);
                float sim = -sqrtf(d2)*0.125f;
                float p = (jg == ig + 1) ? 0.0f : __expf(sim);  // self mask; pads auto-0 via k2=1e9
                Ps[(ib + a)*33 + jb + jj] = p;
                den[a] += p;
            }
        }
        __syncthreads();

        // stage 2: O[i][d] += sum_j P[i][j] V[d][j]
        #pragma unroll 4
        for (int j = 0; j < 32; j++) {
            float p_[4], v_[4];
            #pragma unroll
            for (int a = 0; a < 4; a++) p_[a] = Ps[(ib+a)*33 + j];
            #pragma unroll
            for (int c = 0; c < 4; c++) v_[c] = Vs[(d0+c)*32 + j];
            #pragma unroll
            for (int a = 0; a < 4; a++)
                #pragma unroll
                for (int c = 0; c < 4; c++)
                    oacc[a][c] += p_[a]*v_[c];
        }
        __syncthreads();
    }

    // reduce denominators across ty (16 partials per query)
    #pragma unroll
    for (int a = 0; a < 4; a++) Ps[(ib+a)*33 + ty] = den[a];
    __syncthreads();
    if (tid < 64) {
        float s = 0.f;
        #pragma unroll
        for (int t = 0; t < 16; t++) s += Ps[tid*33 + t];
        rden[tid] = 1.0f / s;
    }
    __syncthreads();
    #pragma unroll
    for (int a = 0; a < 4; a++) {
        float r = rden[ib + a];
        #pragma unroll
        for (int c = 0; c < 4; c++)
            g_att[(size_t)(bh*DHH + d0 + c)*NN + i0g + ib + a] = oacc[a][c]*r;
    }
}

// ===================== output projection GEMM =====================
__global__ __launch_bounds__(256) void out_gemm_kernel(const float* __restrict__ wout,
                                                       float* __restrict__ out) {
    int b  = blockIdx.z;
    int m0 = blockIdx.y * 64;
    int n0 = blockIdx.x * 64;
    __shared__ float As[16][64];
    __shared__ float Bs[16][64];
    int tid = threadIdx.x;
    int tx = tid & 15, ty = tid >> 4;
    float acc[4][4] = {};
    for (int kt = 0; kt < OO; kt += 16) {
        #pragma unroll
        for (int e = tid; e < 1024; e += 256) {
            int r = e >> 4, c = e & 15;
            As[c][r] = wout[(m0 + r)*OO + kt + c];
        }
        #pragma unroll
        for (int e = tid; e < 1024; e += 256) {
            int c = e >> 6, j = e & 63;
            Bs[c][j] = g_att[(size_t)(b*OO + kt + c)*NN + n0 + j];
        }
        __syncthreads();
        #pragma unroll
        for (int kk = 0; kk < 16; kk++) {
            float4 av = *(const float4*)&As[kk][ty*4];
            float4 bv = *(const float4*)&Bs[kk][tx*4];
            float a_[4] = {av.x, av.y, av.z, av.w};
            float b_[4] = {bv.x, bv.y, bv.z, bv.w};
            #pragma unroll
            for (int a = 0; a < 4; a++)
                #pragma unroll
                for (int e = 0; e < 4; e++)
                    acc[a][e] += a_[a]*b_[e];
        }
        __syncthreads();
    }
    #pragma unroll
    for (int a = 0; a < 4; a++)
        #pragma unroll
        for (int e = 0; e < 4; e++)
            out[(size_t)(b*CC + m0 + ty*4 + a)*NN + n0 + tx*4 + e] = acc[a][e];
}

extern "C" void kernel_launch(void* const* d_in, const int* in_sizes, int n_in,
                              void* d_out, int out_size) {
    const float* fmap    = (const float*)d_in[0];
    const float* gamma   = (const float*)d_in[1];
    const float* w_qk    = (const float*)d_in[2];
    const float* w_v     = (const float*)d_in[3];
    const float* null_kv = (const float*)d_in[4];
    const float* w_out   = (const float*)d_in[5];
    float* out = (float*)d_out;

    rms_sumsq_kernel<<<BB*72, 256>>>(fmap);
    rms_norm_kernel<<<BB*CC*NN/256, 256>>>(fmap, gamma);
    proj_gemm_kernel<<<dim3(36, 8, 4), 256>>>(w_qk, w_v);
    fill_null_kernel<<<4, 256>>>(null_kv);
    k2_kernel<<<BB*HH*NKP/256, 256>>>();
    attn_kernel<<<dim3(36, 16), 256>>>();
    out_gemm_kernel<<<dim3(36, 4, 2), 256>>>(w_out, out);
}

// round 3
// speedup vs baseline: 3.0189x; 3.0189x over previous
#include <cuda_runtime.h>
#include <cuda_bf16.h>
#include <cstdint>

#define BB  2
#define CC  256
#define NN  2304
#define HH  8
#define DHH 64
#define OO  512
#define NK  2305
#define NKP 2368          // 1 null + 2304 + 63 pad = 37*64
#define NJ  64
#define NBLK (NKP/NJ)     // 37
#define MT  128
#define NIT (NN/MT)       // 18

// ---- scratch (device globals; no allocation allowed) ----
__device__ float g_norm[BB*CC*NN];
__device__ float g_scale[BB*NN];
__device__ float g_k[BB*HH*DHH*NKP];            // fp32 keys (bh, d, j)
__device__ float g_v[BB*HH*DHH*NKP];            // fp32 values (bh, d, j)
__device__ float g_k2[BB*HH*NKP];               // |k_j|^2 (1e9 on pad)
__device__ __nv_bfloat16 g_kh[BB*HH*NKP*DHH];   // bf16 keys (bh, j, d)  [also serves Q]
__device__ __nv_bfloat16 g_vh[BB*HH*DHH*NKP];   // bf16 V hi (bh, d, j)
__device__ __nv_bfloat16 g_vl[BB*HH*DHH*NKP];   // bf16 V lo (bh, d, j)
__device__ float g_att[BB*OO*NN];

static __device__ __forceinline__ uint32_t s2u(const void* p){
    uint32_t a;
    asm("{ .reg .u64 t; cvta.to.shared.u64 t, %1; cvt.u32.u64 %0, t; }" : "=r"(a) : "l"(p));
    return a;
}

__device__ __forceinline__ void ldsm4(uint32_t* r, uint32_t addr){
    asm volatile("ldmatrix.sync.aligned.m8n8.x4.shared.b16 {%0,%1,%2,%3}, [%4];"
        : "=r"(r[0]), "=r"(r[1]), "=r"(r[2]), "=r"(r[3]) : "r"(addr));
}
__device__ __forceinline__ void mma16816(float* c, const uint32_t* a, uint32_t b0, uint32_t b1){
    asm volatile("mma.sync.aligned.m16n8k16.row.col.f32.bf16.bf16.f32 "
        "{%0,%1,%2,%3}, {%4,%5,%6,%7}, {%8,%9}, {%0,%1,%2,%3};"
        : "+f"(c[0]), "+f"(c[1]), "+f"(c[2]), "+f"(c[3])
        : "r"(a[0]), "r"(a[1]), "r"(a[2]), "r"(a[3]), "r"(b0), "r"(b1));
}
__device__ __forceinline__ uint32_t pack_bf2(float x, float y){
    __nv_bfloat162 t = __floats2bfloat162_rn(x, y);
    return *reinterpret_cast<uint32_t*>(&t);
}

// ===================== RMSNorm =====================
__global__ __launch_bounds__(256) void rms_sumsq_kernel(const float* __restrict__ fmap) {
    __shared__ float part[8][32];
    int b  = blockIdx.x / 72;
    int p0 = (blockIdx.x % 72) * 32;
    int w = threadIdx.x >> 5, l = threadIdx.x & 31;
    int p = p0 + l;
    float s = 0.f;
    #pragma unroll
    for (int c = w; c < CC; c += 8) {
        float v = fmap[(b*CC + c)*NN + p];
        s += v*v;
    }
    part[w][l] = s;
    __syncthreads();
    if (w == 0) {
        float t = 0.f;
        #pragma unroll
        for (int i = 0; i < 8; i++) t += part[i][l];
        g_scale[b*NN + p] = 16.0f / fmaxf(sqrtf(t), 1e-12f);
    }
}

__global__ __launch_bounds__(256) void rms_norm_kernel(const float* __restrict__ fmap,
                                                       const float* __restrict__ gamma) {
    int idx = blockIdx.x*256 + threadIdx.x;
    int p = idx % NN;
    int c = (idx / NN) % CC;
    int b = idx / (CC*NN);
    g_norm[idx] = fmap[idx] * g_scale[b*NN + p] * gamma[c];
}

// ===================== QK / V projection GEMM (fp32) =====================
__global__ __launch_bounds__(256) void proj_gemm_kernel(const float* __restrict__ wqk,
                                                        const float* __restrict__ wv) {
    int z = blockIdx.z;
    int b = z >> 1;
    const float* W = (z & 1) ? wv : wqk;
    float* dst = ((z & 1) ? g_v : g_k) + (size_t)b*HH*DHH*NKP;
    int o0 = blockIdx.y * 64;
    int n0 = blockIdx.x * 64;
    __shared__ float As[16][64];
    __shared__ float Bs[16][64];
    int tid = threadIdx.x;
    int tx = tid & 15, ty = tid >> 4;
    float acc[4][4] = {};
    for (int kt = 0; kt < CC; kt += 16) {
        #pragma unroll
        for (int e = tid; e < 1024; e += 256) {
            int r = e >> 4, c = e & 15;
            As[c][r] = W[(o0 + r)*CC + kt + c];
        }
        #pragma unroll
        for (int e = tid; e < 1024; e += 256) {
            int c = e >> 6, j = e & 63;
            Bs[c][j] = g_norm[(size_t)(b*CC + kt + c)*NN + n0 + j];
        }
        __syncthreads();
        #pragma unroll
        for (int kk = 0; kk < 16; kk++) {
            float4 av = *(const float4*)&As[kk][ty*4];
            float4 bv = *(const float4*)&Bs[kk][tx*4];
            float a_[4] = {av.x, av.y, av.z, av.w};
            float b_[4] = {bv.x, bv.y, bv.z, bv.w};
            #pragma unroll
            for (int a = 0; a < 4; a++)
                #pragma unroll
                for (int e = 0; e < 4; e++)
                    acc[a][e] += a_[a]*b_[e];
        }
        __syncthreads();
    }
    #pragma unroll
    for (int a = 0; a < 4; a++)
        #pragma unroll
        for (int e = 0; e < 4; e++)
            dst[(size_t)(o0 + ty*4 + a)*NKP + n0 + tx*4 + e + 1] = acc[a][e];
}

// ===================== null token + pad fill (parallel) =====================
__global__ __launch_bounds__(256) void fill_null_kernel(const float* __restrict__ null_kv) {
    int tid = blockIdx.x*256 + threadIdx.x;   // 65536
    int slot  = tid & 63;
    int rowid = tid >> 6;
    int d = rowid & 63;
    int h = (rowid >> 6) & 7;
    size_t row = (size_t)rowid * NKP;
    if (slot == 0) {
        g_k[row] = null_kv[h*DHH + d];
        g_v[row] = null_kv[HH*DHH + h*DHH + d];
    } else {
        int j = NK - 1 + slot;   // 2305..2367
        g_k[row + j] = 0.f;
        g_v[row + j] = 0.f;
    }
}

// ===================== k2 =====================
__global__ __launch_bounds__(256) void k2_kernel() {
    int tid = blockIdx.x*256 + threadIdx.x;   // 37888
    int j  = tid % NKP;
    int bh = tid / NKP;
    if (j >= NK) { g_k2[tid] = 1e9f; return; }
    const float* base = g_k + (size_t)bh*DHH*NKP + j;
    float s = 0.f;
    #pragma unroll
    for (int d = 0; d < DHH; d++) { float v = base[(size_t)d*NKP]; s += v*v; }
    g_k2[tid] = s;
}

// ===================== K -> bf16 (transpose to j-major) =====================
__global__ __launch_bounds__(256) void khconv_kernel() {
    __shared__ float ts[32][65];
    int bh = blockIdx.y, j0 = blockIdx.x * 32;
    int tid = threadIdx.x;
    #pragma unroll
    for (int e = tid; e < 2048; e += 256) {
        int d = e >> 5, jj = e & 31;
        ts[jj][d] = g_k[((size_t)bh*DHH + d)*NKP + j0 + jj];
    }
    __syncthreads();
    #pragma unroll
    for (int e = tid; e < 2048; e += 256) {
        int jj = e >> 6, d = e & 63;
        g_kh[((size_t)bh*NKP + j0 + jj)*DHH + d] = __float2bfloat16(ts[jj][d]);
    }
}

// ===================== V -> bf16 hi/lo =====================
__global__ __launch_bounds__(256) void vconv_kernel() {
    size_t i = (size_t)blockIdx.x*256 + threadIdx.x;
    float v = g_v[i];
    __nv_bfloat16 h = __float2bfloat16(v);
    g_vh[i] = h;
    g_vl[i] = __float2bfloat16(v - __bfloat162float(h));
}

// ===================== mma.sync attention =====================
// smem: Q 128x128B @0 (16KB), K 64x128B @16384, Vh @24576, Vl @32768, k2s @40960
#define SM_Q   0
#define SM_K   16384
#define SM_VH  24576
#define SM_VL  32768
#define SM_K2  40960
#define SM_TOT 41216

__global__ __launch_bounds__(256, 2) void attn_mma_kernel() {
    __shared__ __align__(1024) unsigned char sb[SM_TOT];
    const int tid  = threadIdx.x;
    const int lane = tid & 31;
    const int warp = tid >> 5;
    const int bh   = blockIdx.y;
    const int i0   = blockIdx.x * MT;
    const uint32_t smem = s2u(sb);
    float* k2s = (float*)(sb + SM_K2);

    // ---- fill Q tile (swizzled): rows = queries, 64 bf16 each ----
    {
        const uint4* src = (const uint4*)(g_kh + ((size_t)bh*NKP + i0 + 1)*DHH);
        #pragma unroll
        for (int e = tid; e < 1024; e += 256) {
            int row = e >> 3, ch = e & 7;
            *(uint4*)(sb + SM_Q + row*128 + ((ch*16) ^ ((row & 7) << 4))) = src[row*8 + ch];
        }
    }
    __syncthreads();

    // ---- Q fragments (resident) ----
    uint32_t qa[4][4];
    {
        int qo = ((lane >> 3) & 1)*8 + (lane & 7);
        int qsel = ((lane >> 4) & 1)*8;
        uint32_t rowbase = smem + SM_Q + (warp*16 + qo)*128;
        int swz = (qo & 7) << 4;
        #pragma unroll
        for (int kc = 0; kc < 4; kc++)
            ldsm4(qa[kc], rowbase + (((kc*16 + qsel)*2) ^ swz));
    }

    const int r0g = i0 + warp*16 + (lane >> 2);  // global row of c0/c1
    const float q2_0 = g_k2[(size_t)bh*NKP + r0g + 1];
    const float q2_1 = g_k2[(size_t)bh*NKP + r0g + 9];
    float den0 = 0.f, den1 = 0.f;
    float O[8][4] = {};

    // shared lane-geometry for K and V ldmatrix (both non-trans)
    const int jo   = ((lane >> 4) & 1)*8 + (lane & 7);
    const int dsel = ((lane >> 3) & 1)*8;
    const int jswz = (jo & 7) << 4;

    const uint4* kbase = (const uint4*)(g_kh + (size_t)bh*NKP*DHH);
    const char*  vhb   = (const char*)g_vh + (size_t)bh*DHH*NKP*2;
    const char*  vlb   = (const char*)g_vl + (size_t)bh*DHH*NKP*2;
    const float* k2g   = g_k2 + (size_t)bh*NKP;

    for (int blk = 0; blk < NBLK; blk++) {
        const int j0 = blk * NJ;
        // ---- fill K (rows j, cols d) and Vh/Vl (rows d, cols j), swizzled ----
        {
            const uint4* ks = kbase + (size_t)j0*8;
            #pragma unroll
            for (int e = tid; e < 512; e += 256) {
                int row = e >> 3, ch = e & 7;
                uint32_t so = row*128 + ((ch*16) ^ ((row & 7) << 4));
                *(uint4*)(sb + SM_K  + so) = ks[row*8 + ch];
                *(uint4*)(sb + SM_VH + so) = *(const uint4*)(vhb + ((size_t)row*NKP + j0)*2 + ch*16);
                *(uint4*)(sb + SM_VL + so) = *(const uint4*)(vlb + ((size_t)row*NKP + j0)*2 + ch*16);
            }
            if (tid < NJ) k2s[tid] = k2g[j0 + tid];
        }
        __syncthreads();

        // ---- S = Q K^T ----
        float S[8][4] = {};
        #pragma unroll
        for (int kc = 0; kc < 4; kc++) {
            #pragma unroll
            for (int p = 0; p < 4; p++) {
                uint32_t b[4];
                ldsm4(b, smem + SM_K + (p*16 + jo)*128 + (((kc*16 + dsel)*2) ^ jswz));
                mma16816(S[2*p],   qa[kc], b[0], b[1]);
                mma16816(S[2*p+1], qa[kc], b[2], b[3]);
            }
        }

        // ---- softmax (in place): p = exp(-sqrt(d2)/8), self-masked ----
        #pragma unroll
        for (int nt = 0; nt < 8; nt++) {
            int col0 = nt*8 + (lane & 3)*2;
            float k2a = k2s[col0], k2b = k2s[col0 + 1];
            int jg = j0 + col0;
            #pragma unroll
            for (int half = 0; half < 2; half++) {
                float q2 = half ? q2_1 : q2_0;
                int rg = half ? (r0g + 8) : r0g;
                float c0 = S[nt][2*half], c1 = S[nt][2*half+1];
                float d2a = fmaxf(q2 + k2a - 2.f*c0, 0.f);
                float d2b = fmaxf(q2 + k2b - 2.f*c1, 0.f);
                float sa, sbq;
                asm("sqrt.approx.f32 %0, %1;" : "=f"(sa)  : "f"(d2a));
                asm("sqrt.approx.f32 %0, %1;" : "=f"(sbq) : "f"(d2b));
                float pa = __expf(-sa * 0.125f);
                float pb = __expf(-sbq * 0.125f);
                if (jg     == rg + 1) pa = 0.f;
                if (jg + 1 == rg + 1) pb = 0.f;
                if (half) den1 += pa + pb; else den0 += pa + pb;
                S[nt][2*half] = pa; S[nt][2*half+1] = pb;
            }
        }

        // ---- O += P_hi V_hi + P_lo V_hi + P_hi V_lo ----
        #pragma unroll
        for (int c = 0; c < 4; c++) {
            uint32_t ah[4], al[4];
            #pragma unroll
            for (int t = 0; t < 2; t++) {
                const float* s = S[2*c + t];
                uint32_t h0 = pack_bf2(s[0], s[1]);
                uint32_t h1 = pack_bf2(s[2], s[3]);
                ah[2*t] = h0; ah[2*t+1] = h1;
                __nv_bfloat162 hv0 = *reinterpret_cast<__nv_bfloat162*>(&h0);
                __nv_bfloat162 hv1 = *reinterpret_cast<__nv_bfloat162*>(&h1);
                al[2*t]   = pack_bf2(s[0] - __bfloat162float(hv0.x), s[1] - __bfloat162float(hv0.y));
                al[2*t+1] = pack_bf2(s[2] - __bfloat162float(hv1.x), s[3] - __bfloat162float(hv1.y));
            }
            #pragma unroll
            for (int dtp = 0; dtp < 4; dtp++) {
                uint32_t colb = ((c*16 + dsel)*2) ^ jswz;
                uint32_t vh[4], vl[4];
                ldsm4(vh, smem + SM_VH + (dtp*16 + jo)*128 + colb);
                ldsm4(vl, smem + SM_VL + (dtp*16 + jo)*128 + colb);
                mma16816(O[2*dtp],   ah, vh[0], vh[1]);
                mma16816(O[2*dtp+1], ah, vh[2], vh[3]);
                mma16816(O[2*dtp],   al, vh[0], vh[1]);
                mma16816(O[2*dtp+1], al, vh[2], vh[3]);
                mma16816(O[2*dtp],   ah, vl[0], vl[1]);
                mma16816(O[2*dtp+1], ah, vl[2], vl[3]);
            }
        }
        __syncthreads();
    }

    // ---- denominator reduce within quad (lanes sharing rows) ----
    den0 += __shfl_xor_sync(0xffffffffu, den0, 1);
    den0 += __shfl_xor_sync(0xffffffffu, den0, 2);
    den1 += __shfl_xor_sync(0xffffffffu, den1, 1);
    den1 += __shfl_xor_sync(0xffffffffu, den1, 2);
    float rin0 = 1.f / den0, rin1 = 1.f / den1;

    // ---- write O (d-major) ----
    float* att = g_att + (size_t)bh*DHH*NN;
    #pragma unroll
    for (int dt = 0; dt < 8; dt++) {
        int d0 = dt*8 + (lane & 3)*2;
        att[(size_t)(d0    )*NN + r0g]     = O[dt][0]*rin0;
        att[(size_t)(d0 + 1)*NN + r0g]     = O[dt][1]*rin0;
        att[(size_t)(d0    )*NN + r0g + 8] = O[dt][2]*rin1;
        att[(size_t)(d0 + 1)*NN + r0g + 8] = O[dt][3]*rin1;
    }
}

// ===================== output projection GEMM (fp32) =====================
__global__ __launch_bounds__(256) void out_gemm_kernel(const float* __restrict__ wout,
                                                       float* __restrict__ out) {
    int b  = blockIdx.z;
    int m0 = blockIdx.y * 64;
    int n0 = blockIdx.x * 64;
    __shared__ float As[16][64];
    __shared__ float Bs[16][64];
    int tid = threadIdx.x;
    int tx = tid & 15, ty = tid >> 4;
    float acc[4][4] = {};
    for (int kt = 0; kt < OO; kt += 16) {
        #pragma unroll
        for (int e = tid; e < 1024; e += 256) {
            int r = e >> 4, c = e & 15;
            As[c][r] = wout[(m0 + r)*OO + kt + c];
        }
        #pragma unroll
        for (int e = tid; e < 1024; e += 256) {
            int c = e >> 6, j = e & 63;
            Bs[c][j] = g_att[(size_t)(b*OO + kt + c)*NN + n0 + j];
        }
        __syncthreads();
        #pragma unroll
        for (int kk = 0; kk < 16; kk++) {
            float4 av = *(const float4*)&As[kk][ty*4];
            float4 bv = *(const float4*)&Bs[kk][tx*4];
            float a_[4] = {av.x, av.y, av.z, av.w};
            float b_[4] = {bv.x, bv.y, bv.z, bv.w};
            #pragma unroll
            for (int a = 0; a < 4; a++)
                #pragma unroll
                for (int e = 0; e < 4; e++)
                    acc[a][e] += a_[a]*b_[e];
        }
        __syncthreads();
    }
    #pragma unroll
    for (int a = 0; a < 4; a++)
        #pragma unroll
        for (int e = 0; e < 4; e++)
            out[(size_t)(b*CC + m0 + ty*4 + a)*NN + n0 + tx*4 + e] = acc[a][e];
}

extern "C" void kernel_launch(void* const* d_in, const int* in_sizes, int n_in,
                              void* d_out, int out_size) {
    const float* fmap    = (const float*)d_in[0];
    const float* gamma   = (const float*)d_in[1];
    const float* w_qk    = (const float*)d_in[2];
    const float* w_v     = (const float*)d_in[3];
    const float* null_kv = (const float*)d_in[4];
    const float* w_out   = (const float*)d_in[5];
    float* out = (float*)d_out;

    rms_sumsq_kernel<<<BB*72, 256>>>(fmap);
    rms_norm_kernel<<<BB*CC*NN/256, 256>>>(fmap, gamma);
    proj_gemm_kernel<<<dim3(36, 8, 4), 256>>>(w_qk, w_v);
    fill_null_kernel<<<256, 256>>>(null_kv);
    k2_kernel<<<BB*HH*NKP/256, 256>>>();
    khconv_kernel<<<dim3(NKP/32, BB*HH), 256>>>();
    vconv_kernel<<<BB*HH*DHH*NKP/256, 256>>>();
    attn_mma_kernel<<<dim3(NIT, BB*HH), 256>>>();
    out_gemm_kernel<<<dim3(36, 4, 2), 256>>>(w_out, out);
}

// round 4
// speedup vs baseline: 4.2098x; 1.3945x over previous
#include <cuda_runtime.h>
#include <cuda_bf16.h>
#include <cstdint>

#define BB  2
#define CC  256
#define NN  2304
#define HH  8
#define DHH 64
#define OO  512
#define NKP 2368          // 2304 tokens + null@2304 + 63 pad = 37*64
#define NJ  64
#define NBLK (NKP/NJ)     // 37
#define MT  128
#define NIT (NN/MT)       // 18
#define KP3 768           // 3*256
#define KO3 1536          // 3*512

// ---- scratch (device globals; no allocation allowed) ----
__device__ float g_scale[BB*NN];
__device__ __align__(16) __nv_bfloat16 g_normsp[BB*NN*KP3];   // B for proj: (xh,xh,xl) triples, n-major
__device__ __align__(16) __nv_bfloat16 g_wqk3[OO*KP3];        // A: (wh,wl,wh) triples
__device__ __align__(16) __nv_bfloat16 g_wv3[OO*KP3];
__device__ __align__(16) __nv_bfloat16 g_wo3[CC*KO3];
__device__ __align__(16) __nv_bfloat16 g_kh[BB*HH*NKP*DHH];   // keys (bh, n, d); null@2304
__device__ __align__(16) __nv_bfloat16 g_vh[BB*HH*DHH*NKP];   // V hi (bh, d, n)
__device__ __align__(16) __nv_bfloat16 g_vl[BB*HH*DHH*NKP];   // V lo
__device__ float g_k2[BB*HH*NKP];                             // |k_n|^2, 1e9 on pads
__device__ __align__(16) __nv_bfloat16 g_attsp[BB*NN*KO3];    // B for out: (oh,oh,ol) triples

static __device__ __forceinline__ uint32_t s2u(const void* p){
    uint32_t a;
    asm("{ .reg .u64 t; cvta.to.shared.u64 t, %1; cvt.u32.u64 %0, t; }" : "=r"(a) : "l"(p));
    return a;
}
__device__ __forceinline__ void ldsm4(uint32_t* r, uint32_t addr){
    asm volatile("ldmatrix.sync.aligned.m8n8.x4.shared.b16 {%0,%1,%2,%3}, [%4];"
        : "=r"(r[0]), "=r"(r[1]), "=r"(r[2]), "=r"(r[3]) : "r"(addr));
}
__device__ __forceinline__ void mma16816(float* c, const uint32_t* a, uint32_t b0, uint32_t b1){
    asm volatile("mma.sync.aligned.m16n8k16.row.col.f32.bf16.bf16.f32 "
        "{%0,%1,%2,%3}, {%4,%5,%6,%7}, {%8,%9}, {%0,%1,%2,%3};"
        : "+f"(c[0]), "+f"(c[1]), "+f"(c[2]), "+f"(c[3])
        : "r"(a[0]), "r"(a[1]), "r"(a[2]), "r"(a[3]), "r"(b0), "r"(b1));
}
__device__ __forceinline__ uint32_t pack_bf2(float x, float y){
    __nv_bfloat162 t = __floats2bfloat162_rn(x, y);
    return *reinterpret_cast<uint32_t*>(&t);
}
__device__ __forceinline__ unsigned short bfb(float x){
    __nv_bfloat16 h = __float2bfloat16(x);
    return *reinterpret_cast<unsigned short*>(&h);
}
__device__ __forceinline__ float bff(unsigned short u){
    __nv_bfloat16 h = *reinterpret_cast<__nv_bfloat16*>(&u);
    return __bfloat162float(h);
}

// ===================== RMS sum-of-squares =====================
__global__ __launch_bounds__(256) void rms_sumsq_kernel(const float* __restrict__ fmap) {
    __shared__ float part[8][32];
    int b  = blockIdx.x / 72;
    int p0 = (blockIdx.x % 72) * 32;
    int w = threadIdx.x >> 5, l = threadIdx.x & 31;
    int p = p0 + l;
    float s = 0.f;
    #pragma unroll
    for (int c = w; c < CC; c += 8) {
        float v = fmap[(b*CC + c)*NN + p];
        s += v*v;
    }
    part[w][l] = s;
    __syncthreads();
    if (w == 0) {
        float t = 0.f;
        #pragma unroll
        for (int i = 0; i < 8; i++) t += part[i][l];
        g_scale[b*NN + p] = 16.0f / fmaxf(sqrtf(t), 1e-12f);
    }
}

// ===================== RMS normalize + split + transpose =====================
// writes g_normsp[b][n][3c..3c+2] = (xh, xh, xl)
__global__ __launch_bounds__(256) void rms_split_kernel(const float* __restrict__ fmap,
                                                        const float* __restrict__ gamma) {
    __shared__ float ts[32][33];
    __shared__ float gs[32];
    int bid = blockIdx.x;
    int b = bid / (8*72);
    int rest = bid % (8*72);
    int c0 = (rest / 72)*32;
    int n0 = (rest % 72)*32;
    int tid = threadIdx.x;
    #pragma unroll
    for (int e = tid; e < 1024; e += 256) {
        int cc = e >> 5, nn = e & 31;
        ts[cc][nn] = fmap[((size_t)b*CC + c0 + cc)*NN + n0 + nn];
    }
    if (tid < 32) gs[tid] = gamma[c0 + tid];
    __syncthreads();
    int nn = tid >> 3, cq = (tid & 7)*4;
    float sc = g_scale[b*NN + n0 + nn];
    unsigned short hs[4], ls[4];
    #pragma unroll
    for (int t = 0; t < 4; t++) {
        float x = ts[cq + t][nn] * sc * gs[cq + t];
        hs[t] = bfb(x);
        ls[t] = bfb(x - bff(hs[t]));
    }
    uint32_t* wp = (uint32_t*)((char*)g_normsp + (size_t)(b*NN + n0 + nn)*(KP3*2) + 6*(c0 + cq));
    wp[0] = (uint32_t)hs[0] | ((uint32_t)hs[0] << 16);
    wp[1] = (uint32_t)ls[0] | ((uint32_t)hs[1] << 16);
    wp[2] = (uint32_t)hs[1] | ((uint32_t)ls[1] << 16);
    wp[3] = (uint32_t)hs[2] | ((uint32_t)hs[2] << 16);
    wp[4] = (uint32_t)ls[2] | ((uint32_t)hs[3] << 16);
    wp[5] = (uint32_t)hs[3] | ((uint32_t)ls[3] << 16);
}

// ===================== weight split (wh, wl, wh) =====================
__global__ __launch_bounds__(256) void wsplit_kernel(const float* __restrict__ wqk,
                                                     const float* __restrict__ wv,
                                                     const float* __restrict__ wout) {
    int idx = blockIdx.x*256 + threadIdx.x;   // 393216
    float w;
    unsigned short* d;
    if (idx < 131072)      { w = wqk[idx];           d = (unsigned short*)g_wqk3 + 3*(size_t)idx; }
    else if (idx < 262144) { w = wv[idx - 131072];   d = (unsigned short*)g_wv3  + 3*(size_t)(idx - 131072); }
    else                   { w = wout[idx - 262144]; d = (unsigned short*)g_wo3  + 3*(size_t)(idx - 262144); }
    unsigned short h = bfb(w);
    unsigned short l = bfb(w - bff(h));
    d[0] = h; d[1] = l; d[2] = h;
}

// ===================== null token + pad fill =====================
__global__ __launch_bounds__(256) void fill_null_kernel(const float* __restrict__ null_kv) {
    int tid = blockIdx.x*256 + threadIdx.x;   // 65536
    int slot  = tid & 63;
    int rowid = tid >> 6;        // bh*64 + d
    int d  = rowid & 63;
    int bh = rowid >> 6;
    int h  = bh & 7;
    if (slot == 0) {
        float kv = null_kv[h*DHH + d];
        float vv = null_kv[HH*DHH + h*DHH + d];
        g_kh[((size_t)bh*NKP + NN)*DHH + d] = __float2bfloat16(kv);
        unsigned short hh = bfb(vv);
        ((unsigned short*)g_vh)[((size_t)bh*DHH + d)*NKP + NN] = hh;
        ((unsigned short*)g_vl)[((size_t)bh*DHH + d)*NKP + NN] = bfb(vv - bff(hh));
        if (d == 0) {
            float s = 0.f;
            #pragma unroll
            for (int t = 0; t < 64; t++) { float x = null_kv[h*DHH + t]; s += x*x; }
            g_k2[(size_t)bh*NKP + NN] = s;
        }
    } else {
        int n = NN + slot;   // 2305..2367 pads
        g_kh[((size_t)bh*NKP + n)*DHH + d] = __float2bfloat16(0.f);
        ((unsigned short*)g_vh)[((size_t)bh*DHH + d)*NKP + n] = 0;
        ((unsigned short*)g_vl)[((size_t)bh*DHH + d)*NKP + n] = 0;
        if (d == 0) g_k2[(size_t)bh*NKP + n] = 1e9f;
    }
}

// ===================== projection GEMM (split-bf16 mma, fused epilogue) =====================
// grid (18 n-tiles, 8 heads, 4 b*mat); tile 64(d) x 128(n), K'=768
__global__ __launch_bounds__(256, 2) void proj_mma_kernel() {
    __shared__ __align__(1024) unsigned char sb[33024];   // A 8KB @0, B 16KB @8192; reused as Cs[64][129] f32
    const int tid = threadIdx.x, lane = tid & 31, warp = tid >> 5;
    const int b = blockIdx.z >> 1, mat = blockIdx.z & 1;
    const int h = blockIdx.y, n0 = blockIdx.x * 128;
    const int bh = b*HH + h;
    const uint32_t smem = s2u(sb);
    const char* Wb = (const char*)(mat ? g_wv3 : g_wqk3) + (size_t)h*64*(KP3*2);
    const char* Xb = (const char*)g_normsp + (size_t)(b*NN + n0)*(KP3*2);
    const int wm = warp >> 1, wn = warp & 1;
    const int qo = ((lane>>3)&1)*8 + (lane&7), qsel = ((lane>>4)&1)*8, aswz = (qo&7)<<4;
    const int jo = ((lane>>4)&1)*8 + (lane&7), dsel = ((lane>>3)&1)*8, jswz = (jo&7)<<4;
    float C[8][4] = {};

    for (int ch = 0; ch < 12; ch++) {
        #pragma unroll
        for (int e = tid; e < 512; e += 256) {
            int row = e >> 3, c = e & 7;
            *(uint4*)(sb + row*128 + ((c*16) ^ ((row&7)<<4))) =
                *(const uint4*)(Wb + (size_t)row*(KP3*2) + ch*128 + c*16);
        }
        #pragma unroll
        for (int e = tid; e < 1024; e += 256) {
            int row = e >> 3, c = e & 7;
            *(uint4*)(sb + 8192 + row*128 + ((c*16) ^ ((row&7)<<4))) =
                *(const uint4*)(Xb + (size_t)row*(KP3*2) + ch*128 + c*16);
        }
        __syncthreads();
        #pragma unroll
        for (int kc = 0; kc < 4; kc++) {
            uint32_t a[4];
            ldsm4(a, smem + (wm*16 + qo)*128 + (((kc*16 + qsel)*2) ^ aswz));
            #pragma unroll
            for (int p = 0; p < 4; p++) {
                uint32_t bb[4];
                ldsm4(bb, smem + 8192 + (wn*64 + p*16 + jo)*128 + (((kc*16 + dsel)*2) ^ jswz));
                mma16816(C[2*p],   a, bb[0], bb[1]);
                mma16816(C[2*p+1], a, bb[2], bb[3]);
            }
        }
        __syncthreads();
    }

    // stage C (64 d x 128 n) in smem
    float (*Cs)[129] = (float(*)[129])sb;
    {
        int r = lane >> 2, cb = (lane & 3)*2;
        #pragma unroll
        for (int nt = 0; nt < 8; nt++)
            #pragma unroll
            for (int hf = 0; hf < 2; hf++) {
                Cs[wm*16 + r + 8*hf][wn*64 + nt*8 + cb]     = C[nt][2*hf];
                Cs[wm*16 + r + 8*hf][wn*64 + nt*8 + cb + 1] = C[nt][2*hf+1];
            }
    }
    __syncthreads();

    if (mat == 0) {
        // K: write kh rows (n-major) + k2
        int n = tid >> 1, dh = (tid & 1)*32;
        uint32_t pk[16];
        #pragma unroll
        for (int t = 0; t < 16; t++)
            pk[t] = (uint32_t)bfb(Cs[dh + 2*t][n]) | ((uint32_t)bfb(Cs[dh + 2*t + 1][n]) << 16);
        uint4* dst = (uint4*)(g_kh + ((size_t)bh*NKP + n0 + n)*DHH + dh);
        #pragma unroll
        for (int t = 0; t < 4; t++) dst[t] = ((uint4*)pk)[t];
        if (tid < 128) {
            float s = 0.f;
            #pragma unroll
            for (int d = 0; d < 64; d++) { float v = Cs[d][tid]; s += v*v; }
            g_k2[(size_t)bh*NKP + n0 + tid] = s;
        }
    } else {
        // V: write vh/vl rows (d-major)
        int d = tid >> 2, q = (tid & 3)*32;
        uint32_t ph[16], pl[16];
        #pragma unroll
        for (int t = 0; t < 16; t++) {
            float x0 = Cs[d][q + 2*t], x1 = Cs[d][q + 2*t + 1];
            unsigned short h0 = bfb(x0), h1 = bfb(x1);
            ph[t] = (uint32_t)h0 | ((uint32_t)h1 << 16);
            pl[t] = (uint32_t)bfb(x0 - bff(h0)) | ((uint32_t)bfb(x1 - bff(h1)) << 16);
        }
        uint4* dh_ = (uint4*)(g_vh + ((size_t)bh*DHH + d)*NKP + n0 + q);
        uint4* dl_ = (uint4*)(g_vl + ((size_t)bh*DHH + d)*NKP + n0 + q);
        #pragma unroll
        for (int t = 0; t < 4; t++) { dh_[t] = ((uint4*)ph)[t]; dl_[t] = ((uint4*)pl)[t]; }
    }
}

// ===================== mma.sync attention =====================
#define SM_Q   0
#define SM_K   16384
#define SM_VH  24576
#define SM_VL  32768
#define SM_K2  40960
#define SM_TOT 41216

__global__ __launch_bounds__(256, 2) void attn_mma_kernel() {
    __shared__ __align__(1024) unsigned char sb[SM_TOT];
    const int tid  = threadIdx.x;
    const int lane = tid & 31;
    const int warp = tid >> 5;
    const int bh   = blockIdx.y;
    const int i0   = blockIdx.x * MT;
    const uint32_t smem = s2u(sb);
    float* k2s = (float*)(sb + SM_K2);

    {
        const uint4* src = (const uint4*)(g_kh + ((size_t)bh*NKP + i0)*DHH);
        #pragma unroll
        for (int e = tid; e < 1024; e += 256) {
            int row = e >> 3, ch = e & 7;
            *(uint4*)(sb + SM_Q + row*128 + ((ch*16) ^ ((row & 7) << 4))) = src[row*8 + ch];
        }
    }
    __syncthreads();

    uint32_t qa[4][4];
    {
        int qo = ((lane >> 3) & 1)*8 + (lane & 7);
        int qsel = ((lane >> 4) & 1)*8;
        uint32_t rowbase = smem + SM_Q + (warp*16 + qo)*128;
        int swz = (qo & 7) << 4;
        #pragma unroll
        for (int kc = 0; kc < 4; kc++)
            ldsm4(qa[kc], rowbase + (((kc*16 + qsel)*2) ^ swz));
    }

    const int r0g = i0 + warp*16 + (lane >> 2);
    const float q2_0 = g_k2[(size_t)bh*NKP + r0g];
    const float q2_1 = g_k2[(size_t)bh*NKP + r0g + 8];
    float den0 = 0.f, den1 = 0.f;
    float O[8][4] = {};

    const int jo   = ((lane >> 4) & 1)*8 + (lane & 7);
    const int dsel = ((lane >> 3) & 1)*8;
    const int jswz = (jo & 7) << 4;

    const uint4* kbase = (const uint4*)(g_kh + (size_t)bh*NKP*DHH);
    const char*  vhb   = (const char*)g_vh + (size_t)bh*DHH*NKP*2;
    const char*  vlb   = (const char*)g_vl + (size_t)bh*DHH*NKP*2;
    const float* k2g   = g_k2 + (size_t)bh*NKP;

    for (int blk = 0; blk < NBLK; blk++) {
        const int j0 = blk * NJ;
        {
            const uint4* ks = kbase + (size_t)j0*8;
            #pragma unroll
            for (int e = tid; e < 512; e += 256) {
                int row = e >> 3, ch = e & 7;
                uint32_t so = row*128 + ((ch*16) ^ ((row & 7) << 4));
                *(uint4*)(sb + SM_K  + so) = ks[row*8 + ch];
                *(uint4*)(sb + SM_VH + so) = *(const uint4*)(vhb + ((size_t)row*NKP + j0)*2 + ch*16);
                *(uint4*)(sb + SM_VL + so) = *(const uint4*)(vlb + ((size_t)row*NKP + j0)*2 + ch*16);
            }
            if (tid < NJ) k2s[tid] = k2g[j0 + tid];
        }
        __syncthreads();

        float S[8][4] = {};
        #pragma unroll
        for (int kc = 0; kc < 4; kc++) {
            #pragma unroll
            for (int p = 0; p < 4; p++) {
                uint32_t b[4];
                ldsm4(b, smem + SM_K + (p*16 + jo)*128 + (((kc*16 + dsel)*2) ^ jswz));
                mma16816(S[2*p],   qa[kc], b[0], b[1]);
                mma16816(S[2*p+1], qa[kc], b[2], b[3]);
            }
        }

        #pragma unroll
        for (int nt = 0; nt < 8; nt++) {
            int col0 = nt*8 + (lane & 3)*2;
            float k2a = k2s[col0], k2b = k2s[col0 + 1];
            int jg = j0 + col0;
            #pragma unroll
            for (int half = 0; half < 2; half++) {
                float q2 = half ? q2_1 : q2_0;
                int rg = half ? (r0g + 8) : r0g;
                float c0 = S[nt][2*half], c1 = S[nt][2*half+1];
                float d2a = fmaxf(q2 + k2a - 2.f*c0, 0.f);
                float d2b = fmaxf(q2 + k2b - 2.f*c1, 0.f);
                float sa, sbq;
                asm("sqrt.approx.f32 %0, %1;" : "=f"(sa)  : "f"(d2a));
                asm("sqrt.approx.f32 %0, %1;" : "=f"(sbq) : "f"(d2b));
                float pa = __expf(-sa * 0.125f);
                float pb = __expf(-sbq * 0.125f);
                if (jg     == rg) pa = 0.f;       // self mask (n == iq)
                if (jg + 1 == rg) pb = 0.f;
                if (half) den1 += pa + pb; else den0 += pa + pb;
                S[nt][2*half] = pa; S[nt][2*half+1] = pb;
            }
        }

        #pragma unroll
        for (int c = 0; c < 4; c++) {
            uint32_t ah[4], al[4];
            #pragma unroll
            for (int t = 0; t < 2; t++) {
                const float* s = S[2*c + t];
                uint32_t h0 = pack_bf2(s[0], s[1]);
                uint32_t h1 = pack_bf2(s[2], s[3]);
                ah[2*t] = h0; ah[2*t+1] = h1;
                __nv_bfloat162 hv0 = *reinterpret_cast<__nv_bfloat162*>(&h0);
                __nv_bfloat162 hv1 = *reinterpret_cast<__nv_bfloat162*>(&h1);
                al[2*t]   = pack_bf2(s[0] - __bfloat162float(hv0.x), s[1] - __bfloat162float(hv0.y));
                al[2*t+1] = pack_bf2(s[2] - __bfloat162float(hv1.x), s[3] - __bfloat162float(hv1.y));
            }
            #pragma unroll
            for (int dtp = 0; dtp < 4; dtp++) {
                uint32_t colb = ((c*16 + dsel)*2) ^ jswz;
                uint32_t vh[4], vl[4];
                ldsm4(vh, smem + SM_VH + (dtp*16 + jo)*128 + colb);
                ldsm4(vl, smem + SM_VL + (dtp*16 + jo)*128 + colb);
                mma16816(O[2*dtp],   ah, vh[0], vh[1]);
                mma16816(O[2*dtp+1], ah, vh[2], vh[3]);
                mma16816(O[2*dtp],   al, vh[0], vh[1]);
                mma16816(O[2*dtp+1], al, vh[2], vh[3]);
                mma16816(O[2*dtp],   ah, vl[0], vl[1]);
                mma16816(O[2*dtp+1], ah, vl[2], vl[3]);
            }
        }
        __syncthreads();
    }

    den0 += __shfl_xor_sync(0xffffffffu, den0, 1);
    den0 += __shfl_xor_sync(0xffffffffu, den0, 2);
    den1 += __shfl_xor_sync(0xffffffffu, den1, 1);
    den1 += __shfl_xor_sync(0xffffffffu, den1, 2);
    float rin0 = 1.f / den0, rin1 = 1.f / den1;

    // ---- write attsp triples (oh, oh, ol) ----
    {
        int bq = bh >> 3, hq = bh & 7;
        char* abase = (char*)g_attsp + (size_t)bq*NN*(KO3*2);
        #pragma unroll
        for (int dt = 0; dt < 8; dt++) {
            int d0 = dt*8 + (lane & 3)*2;
            int k0 = hq*64 + d0;
            {
                float o0 = O[dt][0]*rin0, o1 = O[dt][1]*rin0;
                unsigned short h0 = bfb(o0), h1 = bfb(o1);
                uint32_t* p = (uint32_t*)(abase + (size_t)r0g*(KO3*2) + 6*k0);
                p[0] = (uint32_t)h0 | ((uint32_t)h0 << 16);
                p[1] = (uint32_t)bfb(o0 - bff(h0)) | ((uint32_t)h1 << 16);
                p[2] = (uint32_t)h1 | ((uint32_t)bfb(o1 - bff(h1)) << 16);
            }
            {
                float o0 = O[dt][2]*rin1, o1 = O[dt][3]*rin1;
                unsigned short h0 = bfb(o0), h1 = bfb(o1);
                uint32_t* p = (uint32_t*)(abase + (size_t)(r0g + 8)*(KO3*2) + 6*k0);
                p[0] = (uint32_t)h0 | ((uint32_t)h0 << 16);
                p[1] = (uint32_t)bfb(o0 - bff(h0)) | ((uint32_t)h1 << 16);
                p[2] = (uint32_t)h1 | ((uint32_t)bfb(o1 - bff(h1)) << 16);
            }
        }
    }
}

// ===================== output projection GEMM (split-bf16 mma) =====================
// grid (18, 4, 2); tile 64(m) x 128(n), K'=1536
__global__ __launch_bounds__(256, 2) void out_mma_kernel(float* __restrict__ out) {
    __shared__ __align__(1024) unsigned char sb[24576];   // A 8KB @0, B 16KB @8192
    const int tid = threadIdx.x, lane = tid & 31, warp = tid >> 5;
    const int b = blockIdx.z;
    const int m0 = blockIdx.y * 64, n0 = blockIdx.x * 128;
    const uint32_t smem = s2u(sb);
    const char* Wb = (const char*)g_wo3 + (size_t)m0*(KO3*2);
    const char* Xb = (const char*)g_attsp + (size_t)(b*NN + n0)*(KO3*2);
    const int wm = warp >> 1, wn = warp & 1;
    const int qo = ((lane>>3)&1)*8 + (lane&7), qsel = ((lane>>4)&1)*8, aswz = (qo&7)<<4;
    const int jo = ((lane>>4)&1)*8 + (lane&7), dsel = ((lane>>3)&1)*8, jswz = (jo&7)<<4;
    float C[8][4] = {};

    for (int ch = 0; ch < 24; ch++) {
        #pragma unroll
        for (int e = tid; e < 512; e += 256) {
            int row = e >> 3, c = e & 7;
            *(uint4*)(sb + row*128 + ((c*16) ^ ((row&7)<<4))) =
                *(const uint4*)(Wb + (size_t)row*(KO3*2) + ch*128 + c*16);
        }
        #pragma unroll
        for (int e = tid; e < 1024; e += 256) {
            int row = e >> 3, c = e & 7;
            *(uint4*)(sb + 8192 + row*128 + ((c*16) ^ ((row&7)<<4))) =
                *(const uint4*)(Xb + (size_t)row*(KO3*2) + ch*128 + c*16);
        }
        __syncthreads();
        #pragma unroll
        for (int kc = 0; kc < 4; kc++) {
            uint32_t a[4];
            ldsm4(a, smem + (wm*16 + qo)*128 + (((kc*16 + qsel)*2) ^ aswz));
            #pragma unroll
            for (int p = 0; p < 4; p++) {
                uint32_t bb[4];
                ldsm4(bb, smem + 8192 + (wn*64 + p*16 + jo)*128 + (((kc*16 + dsel)*2) ^ jswz));
                mma16816(C[2*p],   a, bb[0], bb[1]);
                mma16816(C[2*p+1], a, bb[2], bb[3]);
            }
        }
        __syncthreads();
    }

    int r = lane >> 2, cb = (lane & 3)*2;
    #pragma unroll
    for (int nt = 0; nt < 8; nt++)
        #pragma unroll
        for (int hf = 0; hf < 2; hf++) {
            size_t o = (size_t)(b*CC + m0 + wm*16 + r + 8*hf)*NN + n0 + wn*64 + nt*8 + cb;
            out[o]     = C[nt][2*hf];
            out[o + 1] = C[nt][2*hf+1];
        }
}

extern "C" void kernel_launch(void* const* d_in, const int* in_sizes, int n_in,
                              void* d_out, int out_size) {
    const float* fmap    = (const float*)d_in[0];
    const float* gamma   = (const float*)d_in[1];
    const float* w_qk    = (const float*)d_in[2];
    const float* w_v     = (const float*)d_in[3];
    const float* null_kv = (const float*)d_in[4];
    const float* w_out   = (const float*)d_in[5];
    float* out = (float*)d_out;

    rms_sumsq_kernel<<<BB*72, 256>>>(fmap);
    rms_split_kernel<<<BB*8*72, 256>>>(fmap, gamma);
    wsplit_kernel<<<1536, 256>>>(w_qk, w_v, w_out);
    fill_null_kernel<<<256, 256>>>(null_kv);
    proj_mma_kernel<<<dim3(18, 8, 4), 256>>>();
    attn_mma_kernel<<<dim3(NIT, BB*HH), 256>>>();
    out_mma_kernel<<<dim3(18, 4, 2), 256>>>(out);
}

// round 5
// speedup vs baseline: 5.5789x; 1.3252x over previous
#include <cuda_runtime.h>
#include <cuda_fp16.h>
#include <cstdint>

#define BB  2
#define CC  256
#define NN  2304
#define HH  8
#define DHH 64
#define OO  512
#define NKP 2368          // 2304 tokens + null@2304 + 63 pad = 37*64
#define NJ  64
#define NBLK (NKP/NJ)     // 37
#define MT  128
#define NIT (NN/MT)       // 18
#define KP3 768           // 3*256
#define KO3 1536          // 3*512

// ---- scratch (device globals; no allocation allowed) ----
__device__ float g_scale[BB*NN];
__device__ __align__(16) __half g_normsp[BB*NN*KP3];   // B for proj: (xh,xh,xl) triples, n-major
__device__ __align__(16) __half g_wqk3[OO*KP3];        // A: (wh,wl,wh) triples
__device__ __align__(16) __half g_wv3[OO*KP3];
__device__ __align__(16) __half g_wo3[CC*KO3];
__device__ __align__(16) __half g_kh[BB*HH*NKP*DHH];   // keys fp16 (bh, n, d); null@2304
__device__ __align__(16) __half g_vh[BB*HH*DHH*NKP];   // V fp16 (bh, d, n)
__device__ float g_k2[BB*HH*NKP];                      // |k_n|^2 of ROUNDED keys; 1e9 pads
__device__ __align__(16) __half g_attsp[BB*NN*KO3];    // B for out: (oh,oh,ol) triples

static __device__ __forceinline__ uint32_t s2u(const void* p){
    uint32_t a;
    asm("{ .reg .u64 t; cvta.to.shared.u64 t, %1; cvt.u32.u64 %0, t; }" : "=r"(a) : "l"(p));
    return a;
}
__device__ __forceinline__ void ldsm4(uint32_t* r, uint32_t addr){
    asm volatile("ldmatrix.sync.aligned.m8n8.x4.shared.b16 {%0,%1,%2,%3}, [%4];"
        : "=r"(r[0]), "=r"(r[1]), "=r"(r[2]), "=r"(r[3]) : "r"(addr));
}
__device__ __forceinline__ void mma16816h(float* c, const uint32_t* a, uint32_t b0, uint32_t b1){
    asm volatile("mma.sync.aligned.m16n8k16.row.col.f32.f16.f16.f32 "
        "{%0,%1,%2,%3}, {%4,%5,%6,%7}, {%8,%9}, {%0,%1,%2,%3};"
        : "+f"(c[0]), "+f"(c[1]), "+f"(c[2]), "+f"(c[3])
        : "r"(a[0]), "r"(a[1]), "r"(a[2]), "r"(a[3]), "r"(b0), "r"(b1));
}
__device__ __forceinline__ uint32_t pack_h2(float x, float y){
    __half2 t = __floats2half2_rn(x, y);
    return *reinterpret_cast<uint32_t*>(&t);
}
__device__ __forceinline__ unsigned short hfb(float x){
    __half h = __float2half_rn(x);
    return *reinterpret_cast<unsigned short*>(&h);
}
__device__ __forceinline__ float hff(unsigned short u){
    __half h = *reinterpret_cast<__half*>(&u);
    return __half2float(h);
}
__device__ __forceinline__ void cp16(uint32_t d, const void* s){
    asm volatile("cp.async.cg.shared.global [%0], [%1], 16;" :: "r"(d), "l"(s));
}

// ===================== RMS sum-of-squares =====================
__global__ __launch_bounds__(256) void rms_sumsq_kernel(const float* __restrict__ fmap) {
    __shared__ float part[8][32];
    int b  = blockIdx.x / 72;
    int p0 = (blockIdx.x % 72) * 32;
    int w = threadIdx.x >> 5, l = threadIdx.x & 31;
    int p = p0 + l;
    float s = 0.f;
    #pragma unroll
    for (int c = w; c < CC; c += 8) {
        float v = fmap[(b*CC + c)*NN + p];
        s += v*v;
    }
    part[w][l] = s;
    __syncthreads();
    if (w == 0) {
        float t = 0.f;
        #pragma unroll
        for (int i = 0; i < 8; i++) t += part[i][l];
        g_scale[b*NN + p] = 16.0f / fmaxf(sqrtf(t), 1e-12f);
    }
}

// ===================== RMS normalize + split + transpose =====================
__global__ __launch_bounds__(256) void rms_split_kernel(const float* __restrict__ fmap,
                                                        const float* __restrict__ gamma) {
    __shared__ float ts[32][33];
    __shared__ float gs[32];
    int bid = blockIdx.x;
    int b = bid / (8*72);
    int rest = bid % (8*72);
    int c0 = (rest / 72)*32;
    int n0 = (rest % 72)*32;
    int tid = threadIdx.x;
    #pragma unroll
    for (int e = tid; e < 1024; e += 256) {
        int cc = e >> 5, nn = e & 31;
        ts[cc][nn] = fmap[((size_t)b*CC + c0 + cc)*NN + n0 + nn];
    }
    if (tid < 32) gs[tid] = gamma[c0 + tid];
    __syncthreads();
    int nn = tid >> 3, cq = (tid & 7)*4;
    float sc = g_scale[b*NN + n0 + nn];
    unsigned short hs[4], ls[4];
    #pragma unroll
    for (int t = 0; t < 4; t++) {
        float x = ts[cq + t][nn] * sc * gs[cq + t];
        hs[t] = hfb(x);
        ls[t] = hfb(x - hff(hs[t]));
    }
    uint32_t* wp = (uint32_t*)((char*)g_normsp + (size_t)(b*NN + n0 + nn)*(KP3*2) + 6*(c0 + cq));
    wp[0] = (uint32_t)hs[0] | ((uint32_t)hs[0] << 16);
    wp[1] = (uint32_t)ls[0] | ((uint32_t)hs[1] << 16);
    wp[2] = (uint32_t)hs[1] | ((uint32_t)ls[1] << 16);
    wp[3] = (uint32_t)hs[2] | ((uint32_t)hs[2] << 16);
    wp[4] = (uint32_t)ls[2] | ((uint32_t)hs[3] << 16);
    wp[5] = (uint32_t)hs[3] | ((uint32_t)ls[3] << 16);
}

// ===================== weight split (wh, wl, wh) =====================
__global__ __launch_bounds__(256) void wsplit_kernel(const float* __restrict__ wqk,
                                                     const float* __restrict__ wv,
                                                     const float* __restrict__ wout) {
    int idx = blockIdx.x*256 + threadIdx.x;   // 393216
    float w;
    unsigned short* d;
    if (idx < 131072)      { w = wqk[idx];           d = (unsigned short*)g_wqk3 + 3*(size_t)idx; }
    else if (idx < 262144) { w = wv[idx - 131072];   d = (unsigned short*)g_wv3  + 3*(size_t)(idx - 131072); }
    else                   { w = wout[idx - 262144]; d = (unsigned short*)g_wo3  + 3*(size_t)(idx - 262144); }
    unsigned short h = hfb(w);
    unsigned short l = hfb(w - hff(h));
    d[0] = h; d[1] = l; d[2] = h;
}

// ===================== null token + pad fill =====================
__global__ __launch_bounds__(256) void fill_null_kernel(const float* __restrict__ null_kv) {
    int tid = blockIdx.x*256 + threadIdx.x;   // 65536
    int slot  = tid & 63;
    int rowid = tid >> 6;        // bh*64 + d
    int d  = rowid & 63;
    int bh = rowid >> 6;
    int h  = bh & 7;
    if (slot == 0) {
        float kv = null_kv[h*DHH + d];
        float vv = null_kv[HH*DHH + h*DHH + d];
        ((unsigned short*)g_kh)[((size_t)bh*NKP + NN)*DHH + d] = hfb(kv);
        ((unsigned short*)g_vh)[((size_t)bh*DHH + d)*NKP + NN] = hfb(vv);
        if (d == 0) {
            float s = 0.f;
            #pragma unroll
            for (int t = 0; t < 64; t++) { float x = hff(hfb(null_kv[h*DHH + t])); s += x*x; }
            g_k2[(size_t)bh*NKP + NN] = s;
        }
    } else {
        int n = NN + slot;   // 2305..2367 pads
        ((unsigned short*)g_kh)[((size_t)bh*NKP + n)*DHH + d] = 0;
        ((unsigned short*)g_vh)[((size_t)bh*DHH + d)*NKP + n] = 0;
        if (d == 0) g_k2[(size_t)bh*NKP + n] = 1e9f;
    }
}

// ===================== projection GEMM (triple-fp16 mma, fused epilogue) =====================
// grid (18 n-tiles, 8 heads, 4 b*mat); tile 64(d) x 128(n), K'=768
__global__ __launch_bounds__(256, 2) void proj_mma_kernel() {
    __shared__ __align__(1024) unsigned char sb[33024];   // A 8KB @0, B 16KB @8192; reused as Cs[64][129] f32
    const int tid = threadIdx.x, lane = tid & 31, warp = tid >> 5;
    const int b = blockIdx.z >> 1, mat = blockIdx.z & 1;
    const int h = blockIdx.y, n0 = blockIdx.x * 128;
    const int bh = b*HH + h;
    const uint32_t smem = s2u(sb);
    const char* Wb = (const char*)(mat ? g_wv3 : g_wqk3) + (size_t)h*64*(KP3*2);
    const char* Xb = (const char*)g_normsp + (size_t)(b*NN + n0)*(KP3*2);
    const int wm = warp >> 1, wn = warp & 1;
    const int qo = ((lane>>3)&1)*8 + (lane&7), qsel = ((lane>>4)&1)*8, aswz = (qo&7)<<4;
    const int jo = ((lane>>4)&1)*8 + (lane&7), dsel = ((lane>>3)&1)*8, jswz = (jo&7)<<4;
    float C[8][4] = {};

    for (int ch = 0; ch < 12; ch++) {
        #pragma unroll
        for (int e = tid; e < 512; e += 256) {
            int row = e >> 3, c = e & 7;
            *(uint4*)(sb + row*128 + ((c*16) ^ ((row&7)<<4))) =
                *(const uint4*)(Wb + (size_t)row*(KP3*2) + ch*128 + c*16);
        }
        #pragma unroll
        for (int e = tid; e < 1024; e += 256) {
            int row = e >> 3, c = e & 7;
            *(uint4*)(sb + 8192 + row*128 + ((c*16) ^ ((row&7)<<4))) =
                *(const uint4*)(Xb + (size_t)row*(KP3*2) + ch*128 + c*16);
        }
        __syncthreads();
        #pragma unroll
        for (int kc = 0; kc < 4; kc++) {
            uint32_t a[4];
            ldsm4(a, smem + (wm*16 + qo)*128 + (((kc*16 + qsel)*2) ^ aswz));
            #pragma unroll
            for (int p = 0; p < 4; p++) {
                uint32_t bb[4];
                ldsm4(bb, smem + 8192 + (wn*64 + p*16 + jo)*128 + (((kc*16 + dsel)*2) ^ jswz));
                mma16816h(C[2*p],   a, bb[0], bb[1]);
                mma16816h(C[2*p+1], a, bb[2], bb[3]);
            }
        }
        __syncthreads();
    }

    // stage C (64 d x 128 n) in smem
    float (*Cs)[129] = (float(*)[129])sb;
    {
        int r = lane >> 2, cb = (lane & 3)*2;
        #pragma unroll
        for (int nt = 0; nt < 8; nt++)
            #pragma unroll
            for (int hf = 0; hf < 2; hf++) {
                Cs[wm*16 + r + 8*hf][wn*64 + nt*8 + cb]     = C[nt][2*hf];
                Cs[wm*16 + r + 8*hf][wn*64 + nt*8 + cb + 1] = C[nt][2*hf+1];
            }
    }
    __syncthreads();

    if (mat == 0) {
        // K: round to fp16, write kh (n-major), k2 from ROUNDED values
        int n = tid >> 1, dh = (tid & 1)*32;
        uint32_t pk[16];
        float s = 0.f;
        #pragma unroll
        for (int t = 0; t < 16; t++) {
            unsigned short h0 = hfb(Cs[dh + 2*t][n]);
            unsigned short h1 = hfb(Cs[dh + 2*t + 1][n]);
            float r0 = hff(h0), r1 = hff(h1);
            s += r0*r0 + r1*r1;
            pk[t] = (uint32_t)h0 | ((uint32_t)h1 << 16);
        }
        uint4* dst = (uint4*)((char*)g_kh + (((size_t)bh*NKP + n0 + n)*DHH + dh)*2);
        #pragma unroll
        for (int t = 0; t < 4; t++) dst[t] = ((uint4*)pk)[t];
        s += __shfl_xor_sync(0xffffffffu, s, 1);
        if (!(tid & 1)) g_k2[(size_t)bh*NKP + n0 + n] = s;
    } else {
        // V: round to fp16, write vh (d-major)
        int d = tid >> 2, q = (tid & 3)*32;
        uint32_t ph[16];
        #pragma unroll
        for (int t = 0; t < 16; t++)
            ph[t] = (uint32_t)hfb(Cs[d][q + 2*t]) | ((uint32_t)hfb(Cs[d][q + 2*t + 1]) << 16);
        uint4* dh_ = (uint4*)((char*)g_vh + (((size_t)bh*DHH + d)*NKP + n0 + q)*2);
        #pragma unroll
        for (int t = 0; t < 4; t++) dh_[t] = ((uint4*)ph)[t];
    }
}

// ===================== fp16 mma attention with cp.async double-buffer =====================
// smem: Q 16KB @0; buffers: buf0 K@16384 V@24576, buf1 K@32768 V@40960; k2 2x256B @49152
#define SM_KV  16384
#define SM_K2A 49152
#define SM_TOT 49664

__global__ __launch_bounds__(256, 2) void attn_mma_kernel() {
    __shared__ __align__(1024) unsigned char sb[SM_TOT];
    const int tid  = threadIdx.x;
    const int lane = tid & 31;
    const int warp = tid >> 5;
    const int bh   = blockIdx.y;
    const int i0   = blockIdx.x * MT;
    const uint32_t smem = s2u(sb);

    // ---- Q tile (plain loads, swizzled) ----
    {
        const uint4* src = (const uint4*)(g_kh + ((size_t)bh*NKP + i0)*DHH);
        #pragma unroll
        for (int e = tid; e < 1024; e += 256) {
            int row = e >> 3, ch = e & 7;
            *(uint4*)(sb + row*128 + ((ch*16) ^ ((row & 7) << 4))) = src[row*8 + ch];
        }
    }

    const char* kgb = (const char*)g_kh + (size_t)bh*NKP*DHH*2;
    const char* vgb = (const char*)g_vh + (size_t)bh*DHH*NKP*2;
    const float* k2g = g_k2 + (size_t)bh*NKP;

    // issue loads for a block into buffer buf
    auto load_blk = [&](int blk, int buf) {
        int j0 = blk * NJ;
        uint32_t kb = smem + SM_KV + buf*16384;
        uint32_t vb = kb + 8192;
        #pragma unroll
        for (int e = tid; e < 512; e += 256) {
            int row = e >> 3, ch = e & 7;
            uint32_t so = row*128 + ((ch*16) ^ ((row & 7) << 4));
            cp16(kb + so, kgb + ((size_t)(j0 + row)*DHH)*2 + ch*16);
            cp16(vb + so, vgb + ((size_t)row*NKP + j0)*2 + ch*16);
        }
        if (tid < 16) cp16(smem + SM_K2A + buf*256 + tid*16, (const char*)(k2g + j0) + tid*16);
        asm volatile("cp.async.commit_group;" ::: "memory");
    };

    load_blk(0, 0);
    __syncthreads();

    // ---- Q fragments (resident) ----
    uint32_t qa[4][4];
    {
        int qo = ((lane >> 3) & 1)*8 + (lane & 7);
        int qsel = ((lane >> 4) & 1)*8;
        uint32_t rowbase = smem + (warp*16 + qo)*128;
        int swz = (qo & 7) << 4;
        #pragma unroll
        for (int kc = 0; kc < 4; kc++)
            ldsm4(qa[kc], rowbase + (((kc*16 + qsel)*2) ^ swz));
    }

    const int r0g = i0 + warp*16 + (lane >> 2);
    const float q2_0 = k2g[r0g];
    const float q2_1 = k2g[r0g + 8];
    float den0 = 0.f, den1 = 0.f;
    float O[8][4] = {};

    const int jo   = ((lane >> 4) & 1)*8 + (lane & 7);
    const int dsel = ((lane >> 3) & 1)*8;
    const int jswz = (jo & 7) << 4;

    for (int blk = 0; blk < NBLK; blk++) {
        const int j0 = blk * NJ;
        const int buf = blk & 1;
        if (blk + 1 < NBLK) {
            load_blk(blk + 1, buf ^ 1);
            asm volatile("cp.async.wait_group 1;" ::: "memory");
        } else {
            asm volatile("cp.async.wait_group 0;" ::: "memory");
        }
        __syncthreads();

        const uint32_t kb = smem + SM_KV + buf*16384;
        const uint32_t vb = kb + 8192;
        const float* k2s = (const float*)(sb + SM_K2A + buf*256);

        // ---- S = Q K^T ----
        float S[8][4] = {};
        #pragma unroll
        for (int kc = 0; kc < 4; kc++) {
            #pragma unroll
            for (int p = 0; p < 4; p++) {
                uint32_t b[4];
                ldsm4(b, kb + (p*16 + jo)*128 + (((kc*16 + dsel)*2) ^ jswz));
                mma16816h(S[2*p],   qa[kc], b[0], b[1]);
                mma16816h(S[2*p+1], qa[kc], b[2], b[3]);
            }
        }

        // ---- softmax: p = exp(-sqrt(d2)/8), self-masked ----
        #pragma unroll
        for (int nt = 0; nt < 8; nt++) {
            int col0 = nt*8 + (lane & 3)*2;
            float k2a = k2s[col0], k2b = k2s[col0 + 1];
            int jg = j0 + col0;
            #pragma unroll
            for (int half = 0; half < 2; half++) {
                float q2 = half ? q2_1 : q2_0;
                int rg = half ? (r0g + 8) : r0g;
                float c0 = S[nt][2*half], c1 = S[nt][2*half+1];
                float d2a = fmaxf(q2 + k2a - 2.f*c0, 0.f);
                float d2b = fmaxf(q2 + k2b - 2.f*c1, 0.f);
                float sa, sbq;
                asm("sqrt.approx.f32 %0, %1;" : "=f"(sa)  : "f"(d2a));
                asm("sqrt.approx.f32 %0, %1;" : "=f"(sbq) : "f"(d2b));
                float pa = __expf(-sa * 0.125f);
                float pb = __expf(-sbq * 0.125f);
                if (jg     == rg) pa = 0.f;
                if (jg + 1 == rg) pb = 0.f;
                if (half) den1 += pa + pb; else den0 += pa + pb;
                S[nt][2*half] = pa; S[nt][2*half+1] = pb;
            }
        }

        // ---- O += P V (single fp16 pass) ----
        #pragma unroll
        for (int c = 0; c < 4; c++) {
            uint32_t ap[4];
            #pragma unroll
            for (int t = 0; t < 2; t++) {
                const float* s = S[2*c + t];
                ap[2*t]   = pack_h2(s[0], s[1]);
                ap[2*t+1] = pack_h2(s[2], s[3]);
            }
            #pragma unroll
            for (int dtp = 0; dtp < 4; dtp++) {
                uint32_t vh[4];
                ldsm4(vh, vb + (dtp*16 + jo)*128 + (((c*16 + dsel)*2) ^ jswz));
                mma16816h(O[2*dtp],   ap, vh[0], vh[1]);
                mma16816h(O[2*dtp+1], ap, vh[2], vh[3]);
            }
        }
        __syncthreads();
    }

    den0 += __shfl_xor_sync(0xffffffffu, den0, 1);
    den0 += __shfl_xor_sync(0xffffffffu, den0, 2);
    den1 += __shfl_xor_sync(0xffffffffu, den1, 1);
    den1 += __shfl_xor_sync(0xffffffffu, den1, 2);
    float rin0 = 1.f / den0, rin1 = 1.f / den1;

    // ---- write attsp triples (oh, oh, ol) fp16 ----
    {
        int bq = bh >> 3, hq = bh & 7;
        char* abase = (char*)g_attsp + (size_t)bq*NN*(KO3*2);
        #pragma unroll
        for (int dt = 0; dt < 8; dt++) {
            int d0 = dt*8 + (lane & 3)*2;
            int k0 = hq*64 + d0;
            {
                float o0 = O[dt][0]*rin0, o1 = O[dt][1]*rin0;
                unsigned short h0 = hfb(o0), h1 = hfb(o1);
                uint32_t* p = (uint32_t*)(abase + (size_t)r0g*(KO3*2) + 6*k0);
                p[0] = (uint32_t)h0 | ((uint32_t)h0 << 16);
                p[1] = (uint32_t)hfb(o0 - hff(h0)) | ((uint32_t)h1 << 16);
                p[2] = (uint32_t)h1 | ((uint32_t)hfb(o1 - hff(h1)) << 16);
            }
            {
                float o0 = O[dt][2]*rin1, o1 = O[dt][3]*rin1;
                unsigned short h0 = hfb(o0), h1 = hfb(o1);
                uint32_t* p = (uint32_t*)(abase + (size_t)(r0g + 8)*(KO3*2) + 6*k0);
                p[0] = (uint32_t)h0 | ((uint32_t)h0 << 16);
                p[1] = (uint32_t)hfb(o0 - hff(h0)) | ((uint32_t)h1 << 16);
                p[2] = (uint32_t)h1 | ((uint32_t)hfb(o1 - hff(h1)) << 16);
            }
        }
    }
}

// ===================== output projection GEMM (triple-fp16 mma) =====================
__global__ __launch_bounds__(256, 2) void out_mma_kernel(float* __restrict__ out) {
    __shared__ __align__(1024) unsigned char sb[24576];   // A 8KB @0, B 16KB @8192
    const int tid = threadIdx.x, lane = tid & 31, warp = tid >> 5;
    const int b = blockIdx.z;
    const int m0 = blockIdx.y * 64, n0 = blockIdx.x * 128;
    const uint32_t smem = s2u(sb);
    const char* Wb = (const char*)g_wo3 + (size_t)m0*(KO3*2);
    const char* Xb = (const char*)g_attsp + (size_t)(b*NN + n0)*(KO3*2);
    const int wm = warp >> 1, wn = warp & 1;
    const int qo = ((lane>>3)&1)*8 + (lane&7), qsel = ((lane>>4)&1)*8, aswz = (qo&7)<<4;
    const int jo = ((lane>>4)&1)*8 + (lane&7), dsel = ((lane>>3)&1)*8, jswz = (jo&7)<<4;
    float C[8][4] = {};

    for (int ch = 0; ch < 24; ch++) {
        #pragma unroll
        for (int e = tid; e < 512; e += 256) {
            int row = e >> 3, c = e & 7;
            *(uint4*)(sb + row*128 + ((c*16) ^ ((row&7)<<4))) =
                *(const uint4*)(Wb + (size_t)row*(KO3*2) + ch*128 + c*16);
        }
        #pragma unroll
        for (int e = tid; e < 1024; e += 256) {
            int row = e >> 3, c = e & 7;
            *(uint4*)(sb + 8192 + row*128 + ((c*16) ^ ((row&7)<<4))) =
                *(const uint4*)(Xb + (size_t)row*(KO3*2) + ch*128 + c*16);
        }
        __syncthreads();
        #pragma unroll
        for (int kc = 0; kc < 4; kc++) {
            uint32_t a[4];
            ldsm4(a, smem + (wm*16 + qo)*128 + (((kc*16 + qsel)*2) ^ aswz));
            #pragma unroll
            for (int p = 0; p < 4; p++) {
                uint32_t bb[4];
                ldsm4(bb, smem + 8192 + (wn*64 + p*16 + jo)*128 + (((kc*16 + dsel)*2) ^ jswz));
                mma16816h(C[2*p],   a, bb[0], bb[1]);
                mma16816h(C[2*p+1], a, bb[2], bb[3]);
            }
        }
        __syncthreads();
    }

    int r = lane >> 2, cb = (lane & 3)*2;
    #pragma unroll
    for (int nt = 0; nt < 8; nt++)
        #pragma unroll
        for (int hf = 0; hf < 2; hf++) {
            size_t o = (size_t)(b*CC + m0 + wm*16 + r + 8*hf)*NN + n0 + wn*64 + nt*8 + cb;
            out[o]     = C[nt][2*hf];
            out[o + 1] = C[nt][2*hf+1];
        }
}

extern "C" void kernel_launch(void* const* d_in, const int* in_sizes, int n_in,
                              void* d_out, int out_size) {
    const float* fmap    = (const float*)d_in[0];
    const float* gamma   = (const float*)d_in[1];
    const float* w_qk    = (const float*)d_in[2];
    const float* w_v     = (const float*)d_in[3];
    const float* null_kv = (const float*)d_in[4];
    const float* w_out   = (const float*)d_in[5];
    float* out = (float*)d_out;

    rms_sumsq_kernel<<<BB*72, 256>>>(fmap);
    rms_split_kernel<<<BB*8*72, 256>>>(fmap, gamma);
    wsplit_kernel<<<1536, 256>>>(w_qk, w_v, w_out);
    fill_null_kernel<<<256, 256>>>(null_kv);
    proj_mma_kernel<<<dim3(18, 8, 4), 256>>>();
    attn_mma_kernel<<<dim3(NIT, BB*HH), 256>>>();
    out_mma_kernel<<<dim3(18, 4, 2), 256>>>(out);
}

// round 9
// speedup vs baseline: 6.5591x; 1.1757x over previous
#include <cuda_runtime.h>
#include <cuda_fp16.h>
#include <cstdint>

#define BB  2
#define CC  256
#define NN  2304
#define HH  8
#define DHH 64
#define OO  512
#define NKP 2368          // 2304 tokens + null@2304 + 63 pad = 37*64
#define NJ  64
#define NBLK (NKP/NJ)     // 37
#define MT  128
#define NIT (NN/MT)       // 18
#define KP3 768           // 3*256
#define KO3 1536          // 3*512

#define C2F     0.0325213903f    // (0.125*log2e)^2
#define TWO_C2F 0.0650427806f

// ---- scratch (device globals; no allocation allowed) ----
__device__ __align__(16) __half g_normsp[BB*NN*KP3];   // B for proj: (xh,xh,xl) triples, n-major
__device__ __align__(16) __half g_wqk3[OO*KP3];        // A: (wh,wl,wh) triples
__device__ __align__(16) __half g_wv3[OO*KP3];
__device__ __align__(16) __half g_wo3[CC*KO3];
__device__ __align__(16) __half g_kh[BB*HH*NKP*DHH];   // keys fp16 (bh, n, d); null@2304
__device__ __align__(16) __half g_vh[BB*HH*DHH*NKP];   // V fp16 (bh, d, n)
__device__ float g_k2[BB*HH*NKP];                      // C2 * |k_n|^2 of ROUNDED keys; big on pads
__device__ __align__(16) __half g_attsp[BB*NN*KO3];    // B for out: (oh,oh,ol) triples

static __device__ __forceinline__ uint32_t s2u(const void* p){
    uint32_t a;
    asm("{ .reg .u64 t; cvta.to.shared.u64 t, %1; cvt.u32.u64 %0, t; }" : "=r"(a) : "l"(p));
    return a;
}
__device__ __forceinline__ void ldsm4(uint32_t* r, uint32_t addr){
    asm volatile("ldmatrix.sync.aligned.m8n8.x4.shared.b16 {%0,%1,%2,%3}, [%4];"
        : "=r"(r[0]), "=r"(r[1]), "=r"(r[2]), "=r"(r[3]) : "r"(addr));
}
__device__ __forceinline__ void mma16816h(float* c, const uint32_t* a, uint32_t b0, uint32_t b1){
    asm volatile("mma.sync.aligned.m16n8k16.row.col.f32.f16.f16.f32 "
        "{%0,%1,%2,%3}, {%4,%5,%6,%7}, {%8,%9}, {%0,%1,%2,%3};"
        : "+f"(c[0]), "+f"(c[1]), "+f"(c[2]), "+f"(c[3])
        : "r"(a[0]), "r"(a[1]), "r"(a[2]), "r"(a[3]), "r"(b0), "r"(b1));
}
__device__ __forceinline__ uint32_t pack_h2(float x, float y){
    __half2 t = __floats2half2_rn(x, y);
    return *reinterpret_cast<uint32_t*>(&t);
}
__device__ __forceinline__ uint32_t h2ex2(uint32_t x){
    uint32_t r; asm("ex2.approx.f16x2 %0, %1;" : "=r"(r) : "r"(x)); return r;
}
__device__ __forceinline__ float frsqrt(float x){
    float r; asm("rsqrt.approx.f32 %0, %1;" : "=f"(r) : "f"(x)); return r;
}
__device__ __forceinline__ unsigned short hfb(float x){
    __half h = __float2half_rn(x);
    return *reinterpret_cast<unsigned short*>(&h);
}
__device__ __forceinline__ float hff(unsigned short u){
    __half h = *reinterpret_cast<__half*>(&u);
    return __half2float(h);
}
__device__ __forceinline__ void cp16(uint32_t d, const void* s){
    asm volatile("cp.async.cg.shared.global [%0], [%1], 16;" :: "r"(d), "l"(s));
}
#define CP_COMMIT() asm volatile("cp.async.commit_group;" ::: "memory")
#define CP_WAIT1()  asm volatile("cp.async.wait_group 1;" ::: "memory")
#define CP_WAIT0()  asm volatile("cp.async.wait_group 0;" ::: "memory")

// ===================== fused RMSNorm + split + transpose =====================
__global__ __launch_bounds__(256, 2) void rms_fused_kernel(const float* __restrict__ fmap,
                                                           const float* __restrict__ gamma) {
    __shared__ float ts[256][33];
    __shared__ float gs[256];
    __shared__ float part[8][32];
    __shared__ float sc[32];
    int b  = blockIdx.x / 72;
    int n0 = (blockIdx.x % 72) * 32;
    int tid = threadIdx.x;
    gs[tid] = gamma[tid];
    #pragma unroll
    for (int e = tid; e < 8192; e += 256) {
        int cc = e >> 5, nn = e & 31;
        ts[cc][nn] = fmap[((size_t)b*CC + cc)*NN + n0 + nn];
    }
    __syncthreads();
    {
        int w = tid >> 5, l = tid & 31;
        float s = 0.f;
        #pragma unroll
        for (int r = 0; r < 32; r++) { float v = ts[w*32 + r][l]; s += v*v; }
        part[w][l] = s;
    }
    __syncthreads();
    if (tid < 32) {
        float t = 0.f;
        #pragma unroll
        for (int i = 0; i < 8; i++) t += part[i][tid];
        sc[tid] = 16.0f / fmaxf(sqrtf(t), 1e-12f);
    }
    __syncthreads();
    int nn = tid >> 3, cseg = (tid & 7)*32;
    float scv = sc[nn];
    char* rowp = (char*)g_normsp + (size_t)(b*NN + n0 + nn)*(KP3*2) + 6*cseg;
    #pragma unroll
    for (int b8 = 0; b8 < 4; b8++) {
        uint32_t u[12];
        #pragma unroll
        for (int pr = 0; pr < 4; pr++) {
            int c = cseg + b8*8 + pr*2;
            float x0 = ts[c][nn]*scv*gs[c];
            float x1 = ts[c+1][nn]*scv*gs[c+1];
            unsigned short h0 = hfb(x0), l0 = hfb(x0 - hff(h0));
            unsigned short h1 = hfb(x1), l1 = hfb(x1 - hff(h1));
            u[pr*3+0] = (uint32_t)h0 | ((uint32_t)h0 << 16);
            u[pr*3+1] = (uint32_t)l0 | ((uint32_t)h1 << 16);
            u[pr*3+2] = (uint32_t)h1 | ((uint32_t)l1 << 16);
        }
        uint4* wp = (uint4*)(rowp + b8*48);
        wp[0] = ((uint4*)u)[0]; wp[1] = ((uint4*)u)[1]; wp[2] = ((uint4*)u)[2];
    }
}

// ===================== weight split (wh, wl, wh) =====================
__global__ __launch_bounds__(256) void wsplit_kernel(const float* __restrict__ wqk,
                                                     const float* __restrict__ wv,
                                                     const float* __restrict__ wout) {
    int idx = blockIdx.x*256 + threadIdx.x;   // 393216
    float w;
    unsigned short* d;
    if (idx < 131072)      { w = wqk[idx];           d = (unsigned short*)g_wqk3 + 3*(size_t)idx; }
    else if (idx < 262144) { w = wv[idx - 131072];   d = (unsigned short*)g_wv3  + 3*(size_t)(idx - 131072); }
    else                   { w = wout[idx - 262144]; d = (unsigned short*)g_wo3  + 3*(size_t)(idx - 262144); }
    unsigned short h = hfb(w);
    unsigned short l = hfb(w - hff(h));
    d[0] = h; d[1] = l; d[2] = h;
}

// ===================== null token + pad fill =====================
__global__ __launch_bounds__(256) void fill_null_kernel(const float* __restrict__ null_kv) {
    int tid = blockIdx.x*256 + threadIdx.x;   // 65536
    int slot  = tid & 63;
    int rowid = tid >> 6;        // bh*64 + d
    int d  = rowid & 63;
    int bh = rowid >> 6;
    int h  = bh & 7;
    if (slot == 0) {
        float kv = null_kv[h*DHH + d];
        float vv = null_kv[HH*DHH + h*DHH + d];
        ((unsigned short*)g_kh)[((size_t)bh*NKP + NN)*DHH + d] = hfb(kv);
        ((unsigned short*)g_vh)[((size_t)bh*DHH + d)*NKP + NN] = hfb(vv);
        if (d == 0) {
            float s = 0.f;
            #pragma unroll
            for (int t = 0; t < 64; t++) { float x = hff(hfb(null_kv[h*DHH + t])); s += x*x; }
            g_k2[(size_t)bh*NKP + NN] = s * C2F;
        }
    } else {
        int n = NN + slot;   // 2305..2367 pads
        ((unsigned short*)g_kh)[((size_t)bh*NKP + n)*DHH + d] = 0;
        ((unsigned short*)g_vh)[((size_t)bh*DHH + d)*NKP + n] = 0;
        if (d == 0) g_k2[(size_t)bh*NKP + n] = 1e9f;
    }
}

// ===================== projection GEMM (triple-fp16 mma, cp.async, fused epilogue) =====================
// grid (18 n-tiles, 8 heads, 4 b*mat); tile 64(d) x 128(n), K'=768
// smem: bufA0@0 8KB, bufB0@8192 16KB, bufA1@24576, bufB1@32768 (48KB total); Cs overlays
__global__ __launch_bounds__(256, 2) void proj_mma_kernel() {
    __shared__ __align__(1024) unsigned char sb[49152];
    const int tid = threadIdx.x, lane = tid & 31, warp = tid >> 5;
    const int b = blockIdx.z >> 1, mat = blockIdx.z & 1;
    const int h = blockIdx.y, n0 = blockIdx.x * 128;
    const int bh = b*HH + h;
    const uint32_t smem = s2u(sb);
    const char* Wb = (const char*)(mat ? g_wv3 : g_wqk3) + (size_t)h*64*(KP3*2);
    const char* Xb = (const char*)g_normsp + (size_t)(b*NN + n0)*(KP3*2);
    const int wm = warp >> 1, wn = warp & 1;
    const int qo = ((lane>>3)&1)*8 + (lane&7), qsel = ((lane>>4)&1)*8, aswz = (qo&7)<<4;
    const int jo = ((lane>>4)&1)*8 + (lane&7), dsel = ((lane>>3)&1)*8, jswz = (jo&7)<<4;
    float C[8][4] = {};

    auto load_ch = [&](int ch, int buf) {
        uint32_t ab = smem + buf*24576;
        uint32_t bb = ab + 8192;
        #pragma unroll
        for (int e = tid; e < 512; e += 256) {
            int row = e >> 3, c = e & 7;
            cp16(ab + row*128 + ((c*16) ^ ((row&7)<<4)), Wb + (size_t)row*(KP3*2) + ch*128 + c*16);
        }
        #pragma unroll
        for (int e = tid; e < 1024; e += 256) {
            int row = e >> 3, c = e & 7;
            cp16(bb + row*128 + ((c*16) ^ ((row&7)<<4)), Xb + (size_t)row*(KP3*2) + ch*128 + c*16);
        }
        CP_COMMIT();
    };

    load_ch(0, 0);
    for (int ch = 0; ch < 12; ch++) {
        if (ch + 1 < 12) { load_ch(ch + 1, (ch + 1) & 1); CP_WAIT1(); }
        else             { CP_WAIT0(); }
        __syncthreads();
        uint32_t ab = smem + (ch & 1)*24576;
        uint32_t bbuf = ab + 8192;
        #pragma unroll
        for (int kc = 0; kc < 4; kc++) {
            uint32_t a[4];
            ldsm4(a, ab + (wm*16 + qo)*128 + (((kc*16 + qsel)*2) ^ aswz));
            #pragma unroll
            for (int p = 0; p < 4; p++) {
                uint32_t bb[4];
                ldsm4(bb, bbuf + (wn*64 + p*16 + jo)*128 + (((kc*16 + dsel)*2) ^ jswz));
                mma16816h(C[2*p],   a, bb[0], bb[1]);
                mma16816h(C[2*p+1], a, bb[2], bb[3]);
            }
        }
        __syncthreads();
    }

    // stage C (64 d x 128 n) in smem
    float (*Cs)[129] = (float(*)[129])sb;
    {
        int r = lane >> 2, cb = (lane & 3)*2;
        #pragma unroll
        for (int nt = 0; nt < 8; nt++)
            #pragma unroll
            for (int hf = 0; hf < 2; hf++) {
                Cs[wm*16 + r + 8*hf][wn*64 + nt*8 + cb]     = C[nt][2*hf];
                Cs[wm*16 + r + 8*hf][wn*64 + nt*8 + cb + 1] = C[nt][2*hf+1];
            }
    }
    __syncthreads();

    if (mat == 0) {
        // K: round to fp16, write kh (n-major), k2 = C2 * ||k_rounded||^2
        int n = tid >> 1, dh = (tid & 1)*32;
        uint32_t pk[16];
        float s = 0.f;
        #pragma unroll
        for (int t = 0; t < 16; t++) {
            unsigned short h0 = hfb(Cs[dh + 2*t][n]);
            unsigned short h1 = hfb(Cs[dh + 2*t + 1][n]);
            float r0 = hff(h0), r1 = hff(h1);
            s += r0*r0 + r1*r1;
            pk[t] = (uint32_t)h0 | ((uint32_t)h1 << 16);
        }
        uint4* dst = (uint4*)((char*)g_kh + (((size_t)bh*NKP + n0 + n)*DHH + dh)*2);
        #pragma unroll
        for (int t = 0; t < 4; t++) dst[t] = ((uint4*)pk)[t];
        s += __shfl_xor_sync(0xffffffffu, s, 1);
        if (!(tid & 1)) g_k2[(size_t)bh*NKP + n0 + n] = s * C2F;
    } else {
        // V: round to fp16, write vh (d-major)
        int d = tid >> 2, q = (tid & 3)*32;
        uint32_t ph[16];
        #pragma unroll
        for (int t = 0; t < 16; t++)
            ph[t] = (uint32_t)hfb(Cs[d][q + 2*t]) | ((uint32_t)hfb(Cs[d][q + 2*t + 1]) << 16);
        uint4* dh_ = (uint4*)((char*)g_vh + (((size_t)bh*DHH + d)*NKP + n0 + q)*2);
        #pragma unroll
        for (int t = 0; t < 4; t++) dh_[t] = ((uint4*)ph)[t];
    }
}

// ===================== fp16 mma attention =====================
// smem 33,280 B: region0 [0,16384) = Q tile initially, REUSED as buf1 after Q frags
//                region1 [16384,32768) = buf0; k2 2x256B @32768
#define SM_BUF0 16384
#define SM_K2A  32768
#define SM_TOT  33280

__global__ __launch_bounds__(256, 2) void attn_mma_kernel() {
    __shared__ __align__(1024) unsigned char sb[SM_TOT];
    const int tid  = threadIdx.x;
    const int lane = tid & 31;
    const int warp = tid >> 5;
    const int bh   = blockIdx.y;
    const int i0   = blockIdx.x * MT;
    const uint32_t smem = s2u(sb);

    // ---- Q tile into region0 (swizzled) ----
    {
        const uint4* src = (const uint4*)(g_kh + ((size_t)bh*NKP + i0)*DHH);
        #pragma unroll
        for (int e = tid; e < 1024; e += 256) {
            int row = e >> 3, ch = e & 7;
            *(uint4*)(sb + row*128 + ((ch*16) ^ ((row & 7) << 4))) = src[row*8 + ch];
        }
    }

    const char* kgb = (const char*)g_kh + (size_t)bh*NKP*DHH*2;
    const char* vgb = (const char*)g_vh + (size_t)bh*DHH*NKP*2;
    const float* k2g = g_k2 + (size_t)bh*NKP;

    // buf 0 -> region1 (@16384), buf 1 -> region0 (@0, over dead Q)
    auto load_blk = [&](int blk, int buf) {
        int j0 = blk * NJ;
        uint32_t kb = smem + (buf ? 0 : SM_BUF0);
        uint32_t vb = kb + 8192;
        #pragma unroll
        for (int e = tid; e < 512; e += 256) {
            int row = e >> 3, ch = e & 7;
            uint32_t so = row*128 + ((ch*16) ^ ((row & 7) << 4));
            cp16(kb + so, kgb + ((size_t)(j0 + row)*DHH)*2 + ch*16);
            cp16(vb + so, vgb + ((size_t)row*NKP + j0)*2 + ch*16);
        }
        if (tid < 16) cp16(smem + SM_K2A + buf*256 + tid*16, (const char*)(k2g + j0) + tid*16);
        CP_COMMIT();
    };

    load_blk(0, 0);          // into region1, Q untouched
    __syncthreads();

    // ---- Q fragments (resident), then region0 becomes buf1 ----
    uint32_t qa[4][4];
    {
        int qo = ((lane >> 3) & 1)*8 + (lane & 7);
        int qsel = ((lane >> 4) & 1)*8;
        uint32_t rowbase = smem + (warp*16 + qo)*128;
        int swz = (qo & 7) << 4;
        #pragma unroll
        for (int kc = 0; kc < 4; kc++)
            ldsm4(qa[kc], rowbase + (((kc*16 + qsel)*2) ^ swz));
    }
    __syncthreads();         // all warps done reading Q before buf1 writes begin

    const int r0g = i0 + warp*16 + (lane >> 2);
    const float q2_0 = k2g[r0g];        // C2-scaled
    const float q2_1 = k2g[r0g + 8];
    float O[8][4] = {};
    float Oden[4] = {};
    const uint32_t bone = (lane < 4) ? 0x3C003C00u : 0u;   // ones in B col 0

    const int jo   = ((lane >> 4) & 1)*8 + (lane & 7);
    const int dsel = ((lane >> 3) & 1)*8;
    const int jswz = (jo & 7) << 4;

    for (int blk = 0; blk < NBLK; blk++) {
        const int j0 = blk * NJ;
        const int buf = blk & 1;
        if (blk + 1 < NBLK) { load_blk(blk + 1, buf ^ 1); CP_WAIT1(); }
        else                { CP_WAIT0(); }
        __syncthreads();

        const uint32_t kb = smem + (buf ? 0 : SM_BUF0);
        const uint32_t vb = kb + 8192;
        const float* k2s = (const float*)(sb + SM_K2A + buf*256);

        // ---- S = Q K^T ----
        float S[8][4] = {};
        #pragma unroll
        for (int kc = 0; kc < 4; kc++) {
            #pragma unroll
            for (int p = 0; p < 4; p++) {
                uint32_t b[4];
                ldsm4(b, kb + (p*16 + jo)*128 + (((kc*16 + dsel)*2) ^ jswz));
                mma16816h(S[2*p],   qa[kc], b[0], b[1]);
                mma16816h(S[2*p+1], qa[kc], b[2], b[3]);
            }
        }

        // ---- softmax: p = 2^(-sqrt(C2*d2)), packed f16x2 ----
        uint32_t Ph[8][2];
        #pragma unroll
        for (int nt = 0; nt < 8; nt++) {
            int col0 = nt*8 + (lane & 3)*2;
            float k2a = k2s[col0], k2b = k2s[col0 + 1];
            float qa0 = q2_0 + k2a, qb0 = q2_0 + k2b;
            float qa1 = q2_1 + k2a, qb1 = q2_1 + k2b;
            {
                float d2a = fmaxf(fmaf(S[nt][0], -TWO_C2F, qa0), 1e-12f);
                float d2b = fmaxf(fmaf(S[nt][1], -TWO_C2F, qb0), 1e-12f);
                float na = -(d2a * frsqrt(d2a));
                float nb = -(d2b * frsqrt(d2b));
                Ph[nt][0] = h2ex2(pack_h2(na, nb));
            }
            {
                float d2a = fmaxf(fmaf(S[nt][2], -TWO_C2F, qa1), 1e-12f);
                float d2b = fmaxf(fmaf(S[nt][3], -TWO_C2F, qb1), 1e-12f);
                float na = -(d2a * frsqrt(d2a));
                float nb = -(d2b * frsqrt(d2b));
                Ph[nt][1] = h2ex2(pack_h2(na, nb));
            }
        }
        // self-mask: only the 2 blocks whose key range overlaps this CTA's rows
        if (j0 == i0 || j0 == i0 + 64) {
            #pragma unroll
            for (int nt = 0; nt < 8; nt++) {
                int jg = j0 + nt*8 + (lane & 3)*2;
                #pragma unroll
                for (int hf = 0; hf < 2; hf++) {
                    int rg = hf ? (r0g + 8) : r0g;
                    if (jg     == rg) Ph[nt][hf] &= 0xFFFF0000u;
                    if (jg + 1 == rg) Ph[nt][hf] &= 0x0000FFFFu;
                }
            }
        }

        // ---- O += P V ; den += P . 1 ----
        #pragma unroll
        for (int c = 0; c < 4; c++) {
            uint32_t ap[4] = {Ph[2*c][0], Ph[2*c][1], Ph[2*c+1][0], Ph[2*c+1][1]};
            #pragma unroll
            for (int dtp = 0; dtp < 4; dtp++) {
                uint32_t vh[4];
                ldsm4(vh, vb + (dtp*16 + jo)*128 + (((c*16 + dsel)*2) ^ jswz));
                mma16816h(O[2*dtp],   ap, vh[0], vh[1]);
                mma16816h(O[2*dtp+1], ap, vh[2], vh[3]);
            }
            mma16816h(Oden, ap, bone, bone);
        }
        __syncthreads();
    }

    // den lives in C col 0 (lanes with lane%4==0: c0=row, c2=row+8)
    float den0 = __shfl_sync(0xffffffffu, Oden[0], lane & 28);
    float den1 = __shfl_sync(0xffffffffu, Oden[2], lane & 28);
    float rin0 = 1.f / den0, rin1 = 1.f / den1;

    // ---- write attsp triples (oh, oh, ol) fp16 ----
    {
        int bq = bh >> 3, hq = bh & 7;
        char* abase = (char*)g_attsp + (size_t)bq*NN*(KO3*2);
        #pragma unroll
        for (int dt = 0; dt < 8; dt++) {
            int d0 = dt*8 + (lane & 3)*2;
            int k0 = hq*64 + d0;
            {
                float o0 = O[dt][0]*rin0, o1 = O[dt][1]*rin0;
                unsigned short h0 = hfb(o0), h1 = hfb(o1);
                uint32_t* p = (uint32_t*)(abase + (size_t)r0g*(KO3*2) + 6*k0);
                p[0] = (uint32_t)h0 | ((uint32_t)h0 << 16);
                p[1] = (uint32_t)hfb(o0 - hff(h0)) | ((uint32_t)h1 << 16);
                p[2] = (uint32_t)h1 | ((uint32_t)hfb(o1 - hff(h1)) << 16);
            }
            {
                float o0 = O[dt][2]*rin1, o1 = O[dt][3]*rin1;
                unsigned short h0 = hfb(o0), h1 = hfb(o1);
                uint32_t* p = (uint32_t*)(abase + (size_t)(r0g + 8)*(KO3*2) + 6*k0);
                p[0] = (uint32_t)h0 | ((uint32_t)h0 << 16);
                p[1] = (uint32_t)hfb(o0 - hff(h0)) | ((uint32_t)h1 << 16);
                p[2] = (uint32_t)h1 | ((uint32_t)hfb(o1 - hff(h1)) << 16);
            }
        }
    }
}

// ===================== output projection GEMM (triple-fp16 mma, cp.async) =====================
__global__ __launch_bounds__(256, 2) void out_mma_kernel(float* __restrict__ out) {
    __shared__ __align__(1024) unsigned char sb[49152];
    const int tid = threadIdx.x, lane = tid & 31, warp = tid >> 5;
    const int b = blockIdx.z;
    const int m0 = blockIdx.y * 64, n0 = blockIdx.x * 128;
    const uint32_t smem = s2u(sb);
    const char* Wb = (const char*)g_wo3 + (size_t)m0*(KO3*2);
    const char* Xb = (const char*)g_attsp + (size_t)(b*NN + n0)*(KO3*2);
    const int wm = warp >> 1, wn = warp & 1;
    const int qo = ((lane>>3)&1)*8 + (lane&7), qsel = ((lane>>4)&1)*8, aswz = (qo&7)<<4;
    const int jo = ((lane>>4)&1)*8 + (lane&7), dsel = ((lane>>3)&1)*8, jswz = (jo&7)<<4;
    float C[8][4] = {};

    auto load_ch = [&](int ch, int buf) {
        uint32_t ab = smem + buf*24576;
        uint32_t bb = ab + 8192;
        #pragma unroll
        for (int e = tid; e < 512; e += 256) {
            int row = e >> 3, c = e & 7;
            cp16(ab + row*128 + ((c*16) ^ ((row&7)<<4)), Wb + (size_t)row*(KO3*2) + ch*128 + c*16);
        }
        #pragma unroll
        for (int e = tid; e < 1024; e += 256) {
            int row = e >> 3, c = e & 7;
            cp16(bb + row*128 + ((c*16) ^ ((row&7)<<4)), Xb + (size_t)row*(KO3*2) + ch*128 + c*16);
        }
        CP_COMMIT();
    };

    load_ch(0, 0);
    for (int ch = 0; ch < 24; ch++) {
        if (ch + 1 < 24) { load_ch(ch + 1, (ch + 1) & 1); CP_WAIT1(); }
        else             { CP_WAIT0(); }
        __syncthreads();
        uint32_t ab = smem + (ch & 1)*24576;
        uint32_t bbuf = ab + 8192;
        #pragma unroll
        for (int kc = 0; kc < 4; kc++) {
            uint32_t a[4];
            ldsm4(a, ab + (wm*16 + qo)*128 + (((kc*16 + qsel)*2) ^ aswz));
            #pragma unroll
            for (int p = 0; p < 4; p++) {
                uint32_t bb[4];
                ldsm4(bb, bbuf + (wn*64 + p*16 + jo)*128 + (((kc*16 + dsel)*2) ^ jswz));
                mma16816h(C[2*p],   a, bb[0], bb[1]);
                mma16816h(C[2*p+1], a, bb[2], bb[3]);
            }
        }
        __syncthreads();
    }

    int r = lane >> 2, cb = (lane & 3)*2;
    #pragma unroll
    for (int nt = 0; nt < 8; nt++)
        #pragma unroll
        for (int hf = 0; hf < 2; hf++) {
            size_t o = (size_t)(b*CC + m0 + wm*16 + r + 8*hf)*NN + n0 + wn*64 + nt*8 + cb;
            out[o]     = C[nt][2*hf];
            out[o + 1] = C[nt][2*hf+1];
        }
}

extern "C" void kernel_launch(void* const* d_in, const int* in_sizes, int n_in,
                              void* d_out, int out_size) {
    const float* fmap    = (const float*)d_in[0];
    const float* gamma   = (const float*)d_in[1];
    const float* w_qk    = (const float*)d_in[2];
    const float* w_v     = (const float*)d_in[3];
    const float* null_kv = (const float*)d_in[4];
    const float* w_out   = (const float*)d_in[5];
    float* out = (float*)d_out;

    rms_fused_kernel<<<BB*72, 256>>>(fmap, gamma);
    wsplit_kernel<<<1536, 256>>>(w_qk, w_v, w_out);
    fill_null_kernel<<<256, 256>>>(null_kv);
    proj_mma_kernel<<<dim3(18, 8, 4), 256>>>();
    attn_mma_kernel<<<dim3(NIT, BB*HH), 256>>>();
    out_mma_kernel<<<dim3(18, 4, 2), 256>>>(out);
}

// round 11
// speedup vs baseline: 6.7597x; 1.0306x over previous
#include <cuda_runtime.h>
#include <cuda_fp16.h>
#include <cstdint>

#define BB  2
#define CC  256
#define NN  2304
#define HH  8
#define DHH 64
#define OO  512
#define NKP 2368          // 2304 tokens + null@2304 + 63 pad = 37*64
#define NJ  64
#define NBLK (NKP/NJ)     // 37
#define MT  128
#define NIT (NN/MT)       // 18
#define KP3 768           // 3*256
#define KO3 1536          // 3*512

#define C2F     0.0325213903f    // (0.125*log2e)^2
#define TWO_C2F 0.0650427806f

// ---- scratch (device globals; no allocation allowed) ----
__device__ __align__(16) __half g_normsp[BB*NN*KP3];   // B for proj: (xh,xh,xl) triples, n-major
__device__ __align__(16) __half g_wqk3[OO*KP3];        // A: (wh,wl,wh) triples
__device__ __align__(16) __half g_wv3[OO*KP3];
__device__ __align__(16) __half g_wo3[CC*KO3];
__device__ __align__(16) __half g_kh[BB*HH*NKP*DHH];   // keys fp16 (bh, n, d); null@2304
__device__ __align__(16) __half g_vh[BB*HH*DHH*NKP];   // V fp16 (bh, d, n)
__device__ float g_k2[BB*HH*NKP];                      // C2 * |k_n|^2 of ROUNDED keys; big on pads
__device__ __align__(16) __half g_attsp[BB*NN*KO3];    // B for out: (oh,oh,ol) triples

static __device__ __forceinline__ uint32_t s2u(const void* p){
    uint32_t a;
    asm("{ .reg .u64 t; cvta.to.shared.u64 t, %1; cvt.u32.u64 %0, t; }" : "=r"(a) : "l"(p));
    return a;
}
__device__ __forceinline__ void ldsm4(uint32_t* r, uint32_t addr){
    asm volatile("ldmatrix.sync.aligned.m8n8.x4.shared.b16 {%0,%1,%2,%3}, [%4];"
        : "=r"(r[0]), "=r"(r[1]), "=r"(r[2]), "=r"(r[3]) : "r"(addr));
}
__device__ __forceinline__ void mma16816h(float* c, const uint32_t* a, uint32_t b0, uint32_t b1){
    asm volatile("mma.sync.aligned.m16n8k16.row.col.f32.f16.f16.f32 "
        "{%0,%1,%2,%3}, {%4,%5,%6,%7}, {%8,%9}, {%0,%1,%2,%3};"
        : "+f"(c[0]), "+f"(c[1]), "+f"(c[2]), "+f"(c[3])
        : "r"(a[0]), "r"(a[1]), "r"(a[2]), "r"(a[3]), "r"(b0), "r"(b1));
}
__device__ __forceinline__ uint32_t pack_h2(float x, float y){
    __half2 t = __floats2half2_rn(x, y);
    return *reinterpret_cast<uint32_t*>(&t);
}
__device__ __forceinline__ uint32_t h2ex2(uint32_t x){
    uint32_t r; asm("ex2.approx.f16x2 %0, %1;" : "=r"(r) : "r"(x)); return r;
}
__device__ __forceinline__ float fsqrt(float x){
    float r; asm("sqrt.approx.f32 %0, %1;" : "=f"(r) : "f"(x)); return r;
}
__device__ __forceinline__ unsigned short hfb(float x){
    __half h = __float2half_rn(x);
    return *reinterpret_cast<unsigned short*>(&h);
}
__device__ __forceinline__ float hff(unsigned short u){
    __half h = *reinterpret_cast<__half*>(&u);
    return __half2float(h);
}
__device__ __forceinline__ void cp16(uint32_t d, const void* s){
    asm volatile("cp.async.cg.shared.global [%0], [%1], 16;" :: "r"(d), "l"(s));
}
#define CP_COMMIT() asm volatile("cp.async.commit_group;" ::: "memory")
#define CP_WAIT1()  asm volatile("cp.async.wait_group 1;" ::: "memory")
#define CP_WAIT0()  asm volatile("cp.async.wait_group 0;" ::: "memory")

// ===================== fused RMSNorm + split + transpose =====================
__global__ __launch_bounds__(256, 2) void rms_fused_kernel(const float* __restrict__ fmap,
                                                           const float* __restrict__ gamma) {
    __shared__ float ts[256][33];
    __shared__ float gs[256];
    __shared__ float part[8][32];
    __shared__ float sc[32];
    int b  = blockIdx.x / 72;
    int n0 = (blockIdx.x % 72) * 32;
    int tid = threadIdx.x;
    gs[tid] = gamma[tid];
    #pragma unroll
    for (int e = tid; e < 8192; e += 256) {
        int cc = e >> 5, nn = e & 31;
        ts[cc][nn] = fmap[((size_t)b*CC + cc)*NN + n0 + nn];
    }
    __syncthreads();
    {
        int w = tid >> 5, l = tid & 31;
        float s = 0.f;
        #pragma unroll
        for (int r = 0; r < 32; r++) { float v = ts[w*32 + r][l]; s += v*v; }
        part[w][l] = s;
    }
    __syncthreads();
    if (tid < 32) {
        float t = 0.f;
        #pragma unroll
        for (int i = 0; i < 8; i++) t += part[i][tid];
        sc[tid] = 16.0f / fmaxf(sqrtf(t), 1e-12f);
    }
    __syncthreads();
    int nn = tid >> 3, cseg = (tid & 7)*32;
    float scv = sc[nn];
    char* rowp = (char*)g_normsp + (size_t)(b*NN + n0 + nn)*(KP3*2) + 6*cseg;
    #pragma unroll
    for (int b8 = 0; b8 < 4; b8++) {
        uint32_t u[12];
        #pragma unroll
        for (int pr = 0; pr < 4; pr++) {
            int c = cseg + b8*8 + pr*2;
            float x0 = ts[c][nn]*scv*gs[c];
            float x1 = ts[c+1][nn]*scv*gs[c+1];
            unsigned short h0 = hfb(x0), l0 = hfb(x0 - hff(h0));
            unsigned short h1 = hfb(x1), l1 = hfb(x1 - hff(h1));
            u[pr*3+0] = (uint32_t)h0 | ((uint32_t)h0 << 16);
            u[pr*3+1] = (uint32_t)l0 | ((uint32_t)h1 << 16);
            u[pr*3+2] = (uint32_t)h1 | ((uint32_t)l1 << 16);
        }
        uint4* wp = (uint4*)(rowp + b8*48);
        wp[0] = ((uint4*)u)[0]; wp[1] = ((uint4*)u)[1]; wp[2] = ((uint4*)u)[2];
    }
}

// ===================== weight split + null/pad fill (merged) =====================
__global__ __launch_bounds__(256) void prep_kernel(const float* __restrict__ wqk,
                                                   const float* __restrict__ wv,
                                                   const float* __restrict__ wout,
                                                   const float* __restrict__ null_kv) {
    int bid = blockIdx.x;
    if (bid < 1536) {
        int idx = bid*256 + threadIdx.x;   // 393216
        float w;
        unsigned short* d;
        if (idx < 131072)      { w = wqk[idx];           d = (unsigned short*)g_wqk3 + 3*(size_t)idx; }
        else if (idx < 262144) { w = wv[idx - 131072];   d = (unsigned short*)g_wv3  + 3*(size_t)(idx - 131072); }
        else                   { w = wout[idx - 262144]; d = (unsigned short*)g_wo3  + 3*(size_t)(idx - 262144); }
        unsigned short h = hfb(w);
        unsigned short l = hfb(w - hff(h));
        d[0] = h; d[1] = l; d[2] = h;
    } else {
        int tid = (bid - 1536)*256 + threadIdx.x;   // 65536
        int slot  = tid & 63;
        int rowid = tid >> 6;        // bh*64 + d
        int d  = rowid & 63;
        int bh = rowid >> 6;
        int h  = bh & 7;
        if (slot == 0) {
            float kv = null_kv[h*DHH + d];
            float vv = null_kv[HH*DHH + h*DHH + d];
            ((unsigned short*)g_kh)[((size_t)bh*NKP + NN)*DHH + d] = hfb(kv);
            ((unsigned short*)g_vh)[((size_t)bh*DHH + d)*NKP + NN] = hfb(vv);
            if (d == 0) {
                float s = 0.f;
                #pragma unroll
                for (int t = 0; t < 64; t++) { float x = hff(hfb(null_kv[h*DHH + t])); s += x*x; }
                g_k2[(size_t)bh*NKP + NN] = s * C2F;
            }
        } else {
            int n = NN + slot;   // 2305..2367 pads
            ((unsigned short*)g_kh)[((size_t)bh*NKP + n)*DHH + d] = 0;
            ((unsigned short*)g_vh)[((size_t)bh*DHH + d)*NKP + n] = 0;
            if (d == 0) g_k2[(size_t)bh*NKP + n] = 1e9f;
        }
    }
}

// ===================== projection GEMM (triple-fp16 mma, K-split warps, 32-row tiles) =====================
// grid (18 n-tiles, 8 heads, 4 b*mat); CTA tile 64(d) x 128(n), K'=768
// warps: wk(2) x wm(2) x wn(2); warp tile 32(M) x 64(N), each handles 2 of 4 kc per chunk
// smem: bufA0@0 8KB, bufB0@8192 16KB, bufA1@24576, bufB1@32768 (48KB); Cs[64][129] overlays
__global__ __launch_bounds__(256, 2) void proj_mma_kernel() {
    __shared__ __align__(1024) unsigned char sb[49152];
    const int tid = threadIdx.x, lane = tid & 31, warp = tid >> 5;
    const int b = blockIdx.z >> 1, mat = blockIdx.z & 1;
    const int h = blockIdx.y, n0 = blockIdx.x * 128;
    const int bh = b*HH + h;
    const uint32_t smem = s2u(sb);
    const char* Wb = (const char*)(mat ? g_wv3 : g_wqk3) + (size_t)h*64*(KP3*2);
    const char* Xb = (const char*)g_normsp + (size_t)(b*NN + n0)*(KP3*2);
    const int wn = warp & 1, wm = (warp >> 1) & 1, wk = warp >> 2;
    const int qo = ((lane>>3)&1)*8 + (lane&7), qsel = ((lane>>4)&1)*8, aswz = (qo&7)<<4;
    const int jo = ((lane>>4)&1)*8 + (lane&7), dsel = ((lane>>3)&1)*8, jswz = (jo&7)<<4;
    float C0[8][4] = {}, C1[8][4] = {};

    auto load_ch = [&](int ch, int buf) {
        uint32_t ab = smem + buf*24576;
        uint32_t bb = ab + 8192;
        #pragma unroll
        for (int e = tid; e < 512; e += 256) {
            int row = e >> 3, c = e & 7;
            cp16(ab + row*128 + ((c*16) ^ ((row&7)<<4)), Wb + (size_t)row*(KP3*2) + ch*128 + c*16);
        }
        #pragma unroll
        for (int e = tid; e < 1024; e += 256) {
            int row = e >> 3, c = e & 7;
            cp16(bb + row*128 + ((c*16) ^ ((row&7)<<4)), Xb + (size_t)row*(KP3*2) + ch*128 + c*16);
        }
        CP_COMMIT();
    };

    load_ch(0, 0);
    for (int ch = 0; ch < 12; ch++) {
        if (ch + 1 < 12) { load_ch(ch + 1, (ch + 1) & 1); CP_WAIT1(); }
        else             { CP_WAIT0(); }
        __syncthreads();
        uint32_t ab = smem + (ch & 1)*24576;
        uint32_t bbuf = ab + 8192;
        #pragma unroll
        for (int kcl = 0; kcl < 2; kcl++) {
            int kc = wk*2 + kcl;
            uint32_t a0[4], a1[4];
            ldsm4(a0, ab + (wm*32 +      qo)*128 + (((kc*16 + qsel)*2) ^ aswz));
            ldsm4(a1, ab + (wm*32 + 16 + qo)*128 + (((kc*16 + qsel)*2) ^ aswz));
            #pragma unroll
            for (int p = 0; p < 4; p++) {
                uint32_t bb[4];
                ldsm4(bb, bbuf + (wn*64 + p*16 + jo)*128 + (((kc*16 + dsel)*2) ^ jswz));
                mma16816h(C0[2*p],   a0, bb[0], bb[1]);
                mma16816h(C0[2*p+1], a0, bb[2], bb[3]);
                mma16816h(C1[2*p],   a1, bb[0], bb[1]);
                mma16816h(C1[2*p+1], a1, bb[2], bb[3]);
            }
        }
        __syncthreads();
    }

    // K-reduce through Cs: wk=1 store, wk=0 add
    float (*Cs)[129] = (float(*)[129])sb;
    {
        int r = lane >> 2, cb = (lane & 3)*2;
        if (wk) {
            #pragma unroll
            for (int nt = 0; nt < 8; nt++)
                #pragma unroll
                for (int hf = 0; hf < 2; hf++) {
                    Cs[wm*32      + r + 8*hf][wn*64 + nt*8 + cb]     = C0[nt][2*hf];
                    Cs[wm*32      + r + 8*hf][wn*64 + nt*8 + cb + 1] = C0[nt][2*hf+1];
                    Cs[wm*32 + 16 + r + 8*hf][wn*64 + nt*8 + cb]     = C1[nt][2*hf];
                    Cs[wm*32 + 16 + r + 8*hf][wn*64 + nt*8 + cb + 1] = C1[nt][2*hf+1];
                }
        }
        __syncthreads();
        if (!wk) {
            #pragma unroll
            for (int nt = 0; nt < 8; nt++)
                #pragma unroll
                for (int hf = 0; hf < 2; hf++) {
                    Cs[wm*32      + r + 8*hf][wn*64 + nt*8 + cb]     += C0[nt][2*hf];
                    Cs[wm*32      + r + 8*hf][wn*64 + nt*8 + cb + 1] += C0[nt][2*hf+1];
                    Cs[wm*32 + 16 + r + 8*hf][wn*64 + nt*8 + cb]     += C1[nt][2*hf];
                    Cs[wm*32 + 16 + r + 8*hf][wn*64 + nt*8 + cb + 1] += C1[nt][2*hf+1];
                }
        }
    }
    __syncthreads();

    if (mat == 0) {
        // K: round to fp16, write kh (n-major), k2 = C2 * ||k_rounded||^2
        int n = tid >> 1, dh = (tid & 1)*32;
        uint32_t pk[16];
        float s = 0.f;
        #pragma unroll
        for (int t = 0; t < 16; t++) {
            unsigned short h0 = hfb(Cs[dh + 2*t][n]);
            unsigned short h1 = hfb(Cs[dh + 2*t + 1][n]);
            float r0 = hff(h0), r1 = hff(h1);
            s += r0*r0 + r1*r1;
            pk[t] = (uint32_t)h0 | ((uint32_t)h1 << 16);
        }
        uint4* dst = (uint4*)((char*)g_kh + (((size_t)bh*NKP + n0 + n)*DHH + dh)*2);
        #pragma unroll
        for (int t = 0; t < 4; t++) dst[t] = ((uint4*)pk)[t];
        s += __shfl_xor_sync(0xffffffffu, s, 1);
        if (!(tid & 1)) g_k2[(size_t)bh*NKP + n0 + n] = s * C2F;
    } else {
        // V: round to fp16, write vh (d-major)
        int d = tid >> 2, q = (tid & 3)*32;
        uint32_t ph[16];
        #pragma unroll
        for (int t = 0; t < 16; t++)
            ph[t] = (uint32_t)hfb(Cs[d][q + 2*t]) | ((uint32_t)hfb(Cs[d][q + 2*t + 1]) << 16);
        uint4* dh_ = (uint4*)((char*)g_vh + (((size_t)bh*DHH + d)*NKP + n0 + q)*2);
        #pragma unroll
        for (int t = 0; t < 4; t++) dh_[t] = ((uint4*)ph)[t];
    }
}

// ===================== fp16 mma attention =====================
// smem 33,280 B: region0 [0,16384) = Q tile initially, REUSED as buf1 after Q frags
//                region1 [16384,32768) = buf0; k2 2x256B @32768
#define SM_BUF0 16384
#define SM_K2A  32768
#define SM_TOT  33280

__global__ __launch_bounds__(256, 2) void attn_mma_kernel() {
    __shared__ __align__(1024) unsigned char sb[SM_TOT];
    const int tid  = threadIdx.x;
    const int lane = tid & 31;
    const int warp = tid >> 5;
    const int bh   = blockIdx.y;
    const int i0   = blockIdx.x * MT;
    const uint32_t smem = s2u(sb);

    // ---- Q tile into region0 (swizzled) ----
    {
        const uint4* src = (const uint4*)(g_kh + ((size_t)bh*NKP + i0)*DHH);
        #pragma unroll
        for (int e = tid; e < 1024; e += 256) {
            int row = e >> 3, ch = e & 7;
            *(uint4*)(sb + row*128 + ((ch*16) ^ ((row & 7) << 4))) = src[row*8 + ch];
        }
    }

    const char* kgb = (const char*)g_kh + (size_t)bh*NKP*DHH*2;
    const char* vgb = (const char*)g_vh + (size_t)bh*DHH*NKP*2;
    const float* k2g = g_k2 + (size_t)bh*NKP;

    // buf 0 -> region1 (@16384), buf 1 -> region0 (@0, over dead Q)
    auto load_blk = [&](int blk, int buf) {
        int j0 = blk * NJ;
        uint32_t kb = smem + (buf ? 0 : SM_BUF0);
        uint32_t vb = kb + 8192;
        #pragma unroll
        for (int e = tid; e < 512; e += 256) {
            int row = e >> 3, ch = e & 7;
            uint32_t so = row*128 + ((ch*16) ^ ((row & 7) << 4));
            cp16(kb + so, kgb + ((size_t)(j0 + row)*DHH)*2 + ch*16);
            cp16(vb + so, vgb + ((size_t)row*NKP + j0)*2 + ch*16);
        }
        if (tid < 16) cp16(smem + SM_K2A + buf*256 + tid*16, (const char*)(k2g + j0) + tid*16);
        CP_COMMIT();
    };

    load_blk(0, 0);          // into region1, Q untouched
    __syncthreads();

    // ---- Q fragments (resident), then region0 becomes buf1 ----
    uint32_t qa[4][4];
    {
        int qo = ((lane >> 3) & 1)*8 + (lane & 7);
        int qsel = ((lane >> 4) & 1)*8;
        uint32_t rowbase = smem + (warp*16 + qo)*128;
        int swz = (qo & 7) << 4;
        #pragma unroll
        for (int kc = 0; kc < 4; kc++)
            ldsm4(qa[kc], rowbase + (((kc*16 + qsel)*2) ^ swz));
    }
    __syncthreads();         // all warps done reading Q before buf1 writes begin

    const int r0g = i0 + warp*16 + (lane >> 2);
    const float q2_0 = k2g[r0g];        // C2-scaled
    const float q2_1 = k2g[r0g + 8];
    float O[8][4] = {};
    float Oden[4] = {};
    const uint32_t bone = (lane < 4) ? 0x3C003C00u : 0u;   // ones in B col 0

    const int jo   = ((lane >> 4) & 1)*8 + (lane & 7);
    const int dsel = ((lane >> 3) & 1)*8;
    const int jswz = (jo & 7) << 4;

    for (int blk = 0; blk < NBLK; blk++) {
        const int j0 = blk * NJ;
        const int buf = blk & 1;
        if (blk + 1 < NBLK) { load_blk(blk + 1, buf ^ 1); CP_WAIT1(); }
        else                { CP_WAIT0(); }
        __syncthreads();

        const uint32_t kb = smem + (buf ? 0 : SM_BUF0);
        const uint32_t vb = kb + 8192;
        const float* k2s = (const float*)(sb + SM_K2A + buf*256);

        // ---- S = Q K^T ----
        float S[8][4] = {};
        #pragma unroll
        for (int kc = 0; kc < 4; kc++) {
            #pragma unroll
            for (int p = 0; p < 4; p++) {
                uint32_t b[4];
                ldsm4(b, kb + (p*16 + jo)*128 + (((kc*16 + dsel)*2) ^ jswz));
                mma16816h(S[2*p],   qa[kc], b[0], b[1]);
                mma16816h(S[2*p+1], qa[kc], b[2], b[3]);
            }
        }

        // ---- softmax: p = 2^(-sqrt(C2*d2)), packed f16x2 ----
        uint32_t Ph[8][2];
        #pragma unroll
        for (int nt = 0; nt < 8; nt++) {
            int col0 = nt*8 + (lane & 3)*2;
            float k2a = k2s[col0], k2b = k2s[col0 + 1];
            float qa0 = q2_0 + k2a, qb0 = q2_0 + k2b;
            float qa1 = q2_1 + k2a, qb1 = q2_1 + k2b;
            {
                float d2a = fmaxf(fmaf(S[nt][0], -TWO_C2F, qa0), 1e-12f);
                float d2b = fmaxf(fmaf(S[nt][1], -TWO_C2F, qb0), 1e-12f);
                Ph[nt][0] = h2ex2(pack_h2(-fsqrt(d2a), -fsqrt(d2b)));
            }
            {
                float d2a = fmaxf(fmaf(S[nt][2], -TWO_C2F, qa1), 1e-12f);
                float d2b = fmaxf(fmaf(S[nt][3], -TWO_C2F, qb1), 1e-12f);
                Ph[nt][1] = h2ex2(pack_h2(-fsqrt(d2a), -fsqrt(d2b)));
            }
        }
        // self-mask: only the 2 blocks whose key range overlaps this CTA's rows
        if (j0 == i0 || j0 == i0 + 64) {
            #pragma unroll
            for (int nt = 0; nt < 8; nt++) {
                int jg = j0 + nt*8 + (lane & 3)*2;
                #pragma unroll
                for (int hf = 0; hf < 2; hf++) {
                    int rg = hf ? (r0g + 8) : r0g;
                    if (jg     == rg) Ph[nt][hf] &= 0xFFFF0000u;
                    if (jg + 1 == rg) Ph[nt][hf] &= 0x0000FFFFu;
                }
            }
        }

        // ---- O += P V ; den += P . 1 ----
        #pragma unroll
        for (int c = 0; c < 4; c++) {
            uint32_t ap[4] = {Ph[2*c][0], Ph[2*c][1], Ph[2*c+1][0], Ph[2*c+1][1]};
            #pragma unroll
            for (int dtp = 0; dtp < 4; dtp++) {
                uint32_t vh[4];
                ldsm4(vh, vb + (dtp*16 + jo)*128 + (((c*16 + dsel)*2) ^ jswz));
                mma16816h(O[2*dtp],   ap, vh[0], vh[1]);
                mma16816h(O[2*dtp+1], ap, vh[2], vh[3]);
            }
            mma16816h(Oden, ap, bone, bone);
        }
        __syncthreads();
    }

    // den lives in C col 0 (lanes with lane%4==0: c0=row, c2=row+8)
    float den0 = __shfl_sync(0xffffffffu, Oden[0], lane & 28);
    float den1 = __shfl_sync(0xffffffffu, Oden[2], lane & 28);
    float rin0 = 1.f / den0, rin1 = 1.f / den1;

    // ---- write attsp triples (oh, oh, ol) fp16 ----
    {
        int bq = bh >> 3, hq = bh & 7;
        char* abase = (char*)g_attsp + (size_t)bq*NN*(KO3*2);
        #pragma unroll
        for (int dt = 0; dt < 8; dt++) {
            int d0 = dt*8 + (lane & 3)*2;
            int k0 = hq*64 + d0;
            {
                float o0 = O[dt][0]*rin0, o1 = O[dt][1]*rin0;
                unsigned short h0 = hfb(o0), h1 = hfb(o1);
                uint32_t* p = (uint32_t*)(abase + (size_t)r0g*(KO3*2) + 6*k0);
                p[0] = (uint32_t)h0 | ((uint32_t)h0 << 16);
                p[1] = (uint32_t)hfb(o0 - hff(h0)) | ((uint32_t)h1 << 16);
                p[2] = (uint32_t)h1 | ((uint32_t)hfb(o1 - hff(h1)) << 16);
            }
            {
                float o0 = O[dt][2]*rin1, o1 = O[dt][3]*rin1;
                unsigned short h0 = hfb(o0), h1 = hfb(o1);
                uint32_t* p = (uint32_t*)(abase + (size_t)(r0g + 8)*(KO3*2) + 6*k0);
                p[0] = (uint32_t)h0 | ((uint32_t)h0 << 16);
                p[1] = (uint32_t)hfb(o0 - hff(h0)) | ((uint32_t)h1 << 16);
                p[2] = (uint32_t)h1 | ((uint32_t)hfb(o1 - hff(h1)) << 16);
            }
        }
    }
}

// ===================== output projection GEMM (triple-fp16 mma, K-split warps) =====================
// grid (18, 4, 2); CTA tile 64(m) x 128(n), K'=1536; warp tile 32x64, kc split
__global__ __launch_bounds__(256, 2) void out_mma_kernel(float* __restrict__ out) {
    __shared__ __align__(1024) unsigned char sb[49152];
    const int tid = threadIdx.x, lane = tid & 31, warp = tid >> 5;
    const int b = blockIdx.z;
    const int m0 = blockIdx.y * 64, n0 = blockIdx.x * 128;
    const uint32_t smem = s2u(sb);
    const char* Wb = (const char*)g_wo3 + (size_t)m0*(KO3*2);
    const char* Xb = (const char*)g_attsp + (size_t)(b*NN + n0)*(KO3*2);
    const int wn = warp & 1, wm = (warp >> 1) & 1, wk = warp >> 2;
    const int qo = ((lane>>3)&1)*8 + (lane&7), qsel = ((lane>>4)&1)*8, aswz = (qo&7)<<4;
    const int jo = ((lane>>4)&1)*8 + (lane&7), dsel = ((lane>>3)&1)*8, jswz = (jo&7)<<4;
    float C0[8][4] = {}, C1[8][4] = {};

    auto load_ch = [&](int ch, int buf) {
        uint32_t ab = smem + buf*24576;
        uint32_t bb = ab + 8192;
        #pragma unroll
        for (int e = tid; e < 512; e += 256) {
            int row = e >> 3, c = e & 7;
            cp16(ab + row*128 + ((c*16) ^ ((row&7)<<4)), Wb + (size_t)row*(KO3*2) + ch*128 + c*16);
        }
        #pragma unroll
        for (int e = tid; e < 1024; e += 256) {
            int row = e >> 3, c = e & 7;
            cp16(bb + row*128 + ((c*16) ^ ((row&7)<<4)), Xb + (size_t)row*(KO3*2) + ch*128 + c*16);
        }
        CP_COMMIT();
    };

    load_ch(0, 0);
    for (int ch = 0; ch < 24; ch++) {
        if (ch + 1 < 24) { load_ch(ch + 1, (ch + 1) & 1); CP_WAIT1(); }
        else             { CP_WAIT0(); }
        __syncthreads();
        uint32_t ab = smem + (ch & 1)*24576;
        uint32_t bbuf = ab + 8192;
        #pragma unroll
        for (int kcl = 0; kcl < 2; kcl++) {
            int kc = wk*2 + kcl;
            uint32_t a0[4], a1[4];
            ldsm4(a0, ab + (wm*32 +      qo)*128 + (((kc*16 + qsel)*2) ^ aswz));
            ldsm4(a1, ab + (wm*32 + 16 + qo)*128 + (((kc*16 + qsel)*2) ^ aswz));
            #pragma unroll
            for (int p = 0; p < 4; p++) {
                uint32_t bb[4];
                ldsm4(bb, bbuf + (wn*64 + p*16 + jo)*128 + (((kc*16 + dsel)*2) ^ jswz));
                mma16816h(C0[2*p],   a0, bb[0], bb[1]);
                mma16816h(C0[2*p+1], a0, bb[2], bb[3]);
                mma16816h(C1[2*p],   a1, bb[0], bb[1]);
                mma16816h(C1[2*p+1], a1, bb[2], bb[3]);
            }
        }
        __syncthreads();
    }

    // K-reduce: wk=1 stage to Cs, wk=0 add + write out
    float (*Cs)[129] = (float(*)[129])sb;
    int r = lane >> 2, cb = (lane & 3)*2;
    if (wk) {
        #pragma unroll
        for (int nt = 0; nt < 8; nt++)
            #pragma unroll
            for (int hf = 0; hf < 2; hf++) {
                Cs[wm*32      + r + 8*hf][wn*64 + nt*8 + cb]     = C0[nt][2*hf];
                Cs[wm*32      + r + 8*hf][wn*64 + nt*8 + cb + 1] = C0[nt][2*hf+1];
                Cs[wm*32 + 16 + r + 8*hf][wn*64 + nt*8 + cb]     = C1[nt][2*hf];
                Cs[wm*32 + 16 + r + 8*hf][wn*64 + nt*8 + cb + 1] = C1[nt][2*hf+1];
            }
    }
    __syncthreads();
    if (!wk) {
        #pragma unroll
        for (int nt = 0; nt < 8; nt++)
            #pragma unroll
            for (int hf = 0; hf < 2; hf++) {
                {
                    size_t o = (size_t)(b*CC + m0 + wm*32 + r + 8*hf)*NN + n0 + wn*64 + nt*8 + cb;
                    out[o]     = C0[nt][2*hf]   + Cs[wm*32 + r + 8*hf][wn*64 + nt*8 + cb];
                    out[o + 1] = C0[nt][2*hf+1] + Cs[wm*32 + r + 8*hf][wn*64 + nt*8 + cb + 1];
                }
                {
                    size_t o = (size_t)(b*CC + m0 + wm*32 + 16 + r + 8*hf)*NN + n0 + wn*64 + nt*8 + cb;
                    out[o]     = C1[nt][2*hf]   + Cs[wm*32 + 16 + r + 8*hf][wn*64 + nt*8 + cb];
                    out[o + 1] = C1[nt][2*hf+1] + Cs[wm*32 + 16 + r + 8*hf][wn*64 + nt*8 + cb + 1];
                }
            }
    }
}

extern "C" void kernel_launch(void* const* d_in, const int* in_sizes, int n_in,
                              void* d_out, int out_size) {
    const float* fmap    = (const float*)d_in[0];
    const float* gamma   = (const float*)d_in[1];
    const float* w_qk    = (const float*)d_in[2];
    const float* w_v     = (const float*)d_in[3];
    const float* null_kv = (const float*)d_in[4];
    const float* w_out   = (const float*)d_in[5];
    float* out = (float*)d_out;

    rms_fused_kernel<<<BB*72, 256>>>(fmap, gamma);
    prep_kernel<<<1792, 256>>>(w_qk, w_v, w_out, null_kv);
    proj_mma_kernel<<<dim3(18, 8, 4), 256>>>();
    attn_mma_kernel<<<dim3(NIT, BB*HH), 256>>>();
    out_mma_kernel<<<dim3(18, 4, 2), 256>>>(out);
}